// round 5
// baseline (speedup 1.0000x reference)
#include <cuda_runtime.h>
#include <cstdint>
#include <cstddef>

#define NN   50000
#define EE   800000
#define DIN  128
#define DH   256

// ---------------- scratch (device globals; no allocation allowed) ------------
__device__ float g_dinv[NN];             // weighted in-degree -> rsqrt in place
__device__ int   g_count[NN];            // per-dst edge count
__device__ int   g_rowstart[NN + 1];     // CSR offsets
__device__ int   g_cursor[NN];           // fill cursors (copy of offsets)
__device__ int2  g_csr[EE];              // packed (src, nrm-as-bits) per slot
__device__ float g_agg1[NN * DIN];       // A @ x
__device__ float g_h[(size_t)NN * DH];   // relu(agg1 @ W1^T + b1)
__device__ float g_p[NN * DIN];          // h @ W2^T
__device__ int   g_src[EE];              // clean int32 src ids
__device__ int   g_dst[EE];              // clean int32 dst ids
__device__ int   g_is64;

// ---------------- dtype sniffer ----------------------------------------------
__global__ void detect_idx_kernel(const int* __restrict__ raw) {
    __shared__ int nz;
    if (threadIdx.x == 0) nz = 0;
    __syncthreads();
    if (raw[2 * threadIdx.x + 1] != 0) atomicOr(&nz, 1);
    __syncthreads();
    if (threadIdx.x == 0) g_is64 = (nz == 0) ? 1 : 0;
}

// ------- convert indices + weighted in-degree + per-dst edge counts ----------
__global__ void convert_deg_kernel(const void* __restrict__ raw,
                                   const float* __restrict__ w,
                                   int* __restrict__ src,
                                   int* __restrict__ dst,
                                   float* __restrict__ deg,
                                   int* __restrict__ cnt, int e) {
    int i = blockIdx.x * blockDim.x + threadIdx.x;
    if (i >= e) return;
    int s, d;
    if (g_is64) {
        const long long* p = (const long long*)raw;
        s = (int)p[i];
        d = (int)p[(size_t)e + i];
    } else {
        const int* p = (const int*)raw;
        s = p[i];
        d = p[e + i];
    }
    src[i] = s;
    dst[i] = d;
    atomicAdd(&deg[d], w[i]);
    atomicAdd(&cnt[d], 1);
}

__global__ void dinv_kernel(float* deg, int n) {
    int i = blockIdx.x * blockDim.x + threadIdx.x;
    if (i < n) deg[i] = rsqrtf(deg[i] + 1.0f);   // +1 = self-loop weight
}

// ---------------- single-block exclusive scan over counts --------------------
#define SCAN_T 1024
#define SCAN_CHUNK 49        // 1024*49 = 50176 >= 50000
__global__ void scan_kernel(const int* __restrict__ cnt,
                            int* __restrict__ rowstart,
                            int* __restrict__ cursor, int n) {
    __shared__ int part[SCAN_T];
    const int t = threadIdx.x;
    const int base = t * SCAN_CHUNK;
    int s = 0;
#pragma unroll
    for (int i = 0; i < SCAN_CHUNK; i++)
        if (base + i < n) s += cnt[base + i];
    part[t] = s;
    __syncthreads();
    // Hillis-Steele inclusive scan
    for (int off = 1; off < SCAN_T; off <<= 1) {
        int tmp = (t >= off) ? part[t - off] : 0;
        __syncthreads();
        part[t] += tmp;
        __syncthreads();
    }
    int run = part[t] - s;   // exclusive prefix of this thread's chunk
    for (int i = 0; i < SCAN_CHUNK; i++) {
        int idx = base + i;
        if (idx < n) {
            rowstart[idx] = run;
            cursor[idx]   = run;
            run += cnt[idx];
        }
    }
    if (t == SCAN_T - 1) rowstart[n] = run;
}

// ---------------- CSR fill: slot <- (src, norm) ------------------------------
__global__ void csr_fill_kernel(const int* __restrict__ src,
                                const int* __restrict__ dst,
                                const float* __restrict__ w,
                                const float* __restrict__ dinv,
                                int* __restrict__ cursor,
                                int2* __restrict__ csr, int e) {
    int i = blockIdx.x * blockDim.x + threadIdx.x;
    if (i >= e) return;
    int s = src[i], d = dst[i];
    float nrm = dinv[s] * w[i] * dinv[d];
    int pos = atomicAdd(&cursor[d], 1);
    csr[pos] = make_int2(s, __float_as_int(nrm));
}

// ---------------- CSR gather: one warp per node, optional fused LN -----------
// acc initialized with self-loop (feat[d]*dinv[d]^2) -> no zero/init pass.
template <int DO_LN>
__global__ __launch_bounds__(256)
void gather_kernel(const int* __restrict__ rowstart,
                   const int2* __restrict__ csr,
                   const float* __restrict__ dinv,
                   const float* __restrict__ feat,
                   const float* __restrict__ b2,
                   const float* __restrict__ gamma,
                   const float* __restrict__ beta,
                   float* __restrict__ outb, int n) {
    const int node = (blockIdx.x * blockDim.x + threadIdx.x) >> 5;
    const int lane = threadIdx.x & 31;
    if (node >= n) return;

    float dv = dinv[node];
    float4 acc = *(const float4*)(feat + (size_t)node * DIN + lane * 4);
    acc.x *= dv * dv; acc.y *= dv * dv; acc.z *= dv * dv; acc.w *= dv * dv;

    const int beg = rowstart[node];
    const int end = rowstart[node + 1];

    int j = beg;
    // 2x unrolled for MLP
    for (; j + 1 < end; j += 2) {
        int2 e0 = csr[j];
        int2 e1 = csr[j + 1];
        const float4 v0 = *(const float4*)(feat + (size_t)e0.x * DIN + lane * 4);
        const float4 v1 = *(const float4*)(feat + (size_t)e1.x * DIN + lane * 4);
        float n0 = __int_as_float(e0.y), n1 = __int_as_float(e1.y);
        acc.x = fmaf(v0.x, n0, acc.x); acc.y = fmaf(v0.y, n0, acc.y);
        acc.z = fmaf(v0.z, n0, acc.z); acc.w = fmaf(v0.w, n0, acc.w);
        acc.x = fmaf(v1.x, n1, acc.x); acc.y = fmaf(v1.y, n1, acc.y);
        acc.z = fmaf(v1.z, n1, acc.z); acc.w = fmaf(v1.w, n1, acc.w);
    }
    if (j < end) {
        int2 e0 = csr[j];
        const float4 v0 = *(const float4*)(feat + (size_t)e0.x * DIN + lane * 4);
        float n0 = __int_as_float(e0.y);
        acc.x = fmaf(v0.x, n0, acc.x); acc.y = fmaf(v0.y, n0, acc.y);
        acc.z = fmaf(v0.z, n0, acc.z); acc.w = fmaf(v0.w, n0, acc.w);
    }

    if (DO_LN) {
        float4 bb = *(const float4*)(b2 + lane * 4);
        acc.x += bb.x; acc.y += bb.y; acc.z += bb.z; acc.w += bb.w;

        float s = acc.x + acc.y + acc.z + acc.w;
#pragma unroll
        for (int o = 16; o > 0; o >>= 1) s += __shfl_xor_sync(0xFFFFFFFFu, s, o);
        float mu = s * (1.0f / DIN);

        float dx = acc.x - mu, dy = acc.y - mu, dz = acc.z - mu, dw = acc.w - mu;
        float q = dx * dx + dy * dy + dz * dz + dw * dw;
#pragma unroll
        for (int o = 16; o > 0; o >>= 1) q += __shfl_xor_sync(0xFFFFFFFFu, q, o);
        float rstd = rsqrtf(q * (1.0f / DIN) + 1e-5f);

        float4 g  = *(const float4*)(gamma + lane * 4);
        float4 bt = *(const float4*)(beta + lane * 4);
        float4 o4;
        o4.x = dx * rstd * g.x + bt.x;
        o4.y = dy * rstd * g.y + bt.y;
        o4.z = dz * rstd * g.z + bt.z;
        o4.w = dw * rstd * g.w + bt.w;
        *(float4*)(outb + (size_t)node * DIN + lane * 4) = o4;
    } else {
        *(float4*)(outb + (size_t)node * DIN + lane * 4) = acc;
    }
}

// ---------------- TF32 tensor-core GEMM --------------------------------------
__device__ __forceinline__ uint32_t f2tf32(float f) {
    uint32_t u;
    asm("cvt.rna.tf32.f32 %0, %1;" : "=r"(u) : "f"(f));
    return u;
}

__device__ __forceinline__ void mma_tf32(float c[4], const uint32_t a[4],
                                         const uint32_t b[2]) {
    asm volatile(
        "mma.sync.aligned.m16n8k8.row.col.f32.tf32.tf32.f32 "
        "{%0,%1,%2,%3}, {%4,%5,%6,%7}, {%8,%9}, {%0,%1,%2,%3};"
        : "+f"(c[0]), "+f"(c[1]), "+f"(c[2]), "+f"(c[3])
        : "r"(a[0]), "r"(a[1]), "r"(a[2]), "r"(a[3]), "r"(b[0]), "r"(b[1]));
}

#define LDPAD 36

__global__ __launch_bounds__(256)
void gemm_tf32_kernel(const float* __restrict__ A, const float* __restrict__ W,
                      const float* __restrict__ bias, float* __restrict__ C,
                      int M, int K, int Nout, int doRelu) {
    __shared__ uint32_t As[128 * LDPAD];
    __shared__ uint32_t Ws[128 * LDPAD];

    const int tid  = threadIdx.x;
    const int lane = tid & 31;
    const int warp = tid >> 5;
    const int wm   = warp & 3;
    const int wn   = warp >> 2;
    const int gid  = lane >> 2;
    const int tig  = lane & 3;
    const int m0   = blockIdx.x * 128;
    const int n0   = blockIdx.y * 128;

    const int lrow = tid >> 3;
    const int lkq  = tid & 7;

    float acc[2][8][4];
#pragma unroll
    for (int i = 0; i < 2; i++)
#pragma unroll
        for (int j = 0; j < 8; j++)
#pragma unroll
            for (int q = 0; q < 4; q++) acc[i][j][q] = 0.f;

    const int nt = K / 32;
    for (int kt = 0; kt < nt; kt++) {
        const int kbase = kt * 32;
        float4 av[4], wv[4];
#pragma unroll
        for (int l = 0; l < 4; l++) {
            int row = lrow + l * 32;
            av[l] = (m0 + row < M)
                  ? *(const float4*)(A + (size_t)(m0 + row) * K + kbase + lkq * 4)
                  : make_float4(0.f, 0.f, 0.f, 0.f);
            wv[l] = *(const float4*)(W + (size_t)(n0 + row) * K + kbase + lkq * 4);
        }
        if (kt > 0) __syncthreads();
#pragma unroll
        for (int l = 0; l < 4; l++) {
            int row = lrow + l * 32;
            uint4 ua = make_uint4(f2tf32(av[l].x), f2tf32(av[l].y),
                                  f2tf32(av[l].z), f2tf32(av[l].w));
            uint4 uw = make_uint4(f2tf32(wv[l].x), f2tf32(wv[l].y),
                                  f2tf32(wv[l].z), f2tf32(wv[l].w));
            *(uint4*)&As[row * LDPAD + lkq * 4] = ua;
            *(uint4*)&Ws[row * LDPAD + lkq * 4] = uw;
        }
        __syncthreads();

#pragma unroll
        for (int ks = 0; ks < 4; ks++) {
            const int k8 = ks * 8;
            uint32_t af[2][4];
#pragma unroll
            for (int mt = 0; mt < 2; mt++) {
                int rbase = wm * 32 + mt * 16;
                af[mt][0] = As[(rbase + gid) * LDPAD + k8 + tig];
                af[mt][1] = As[(rbase + gid + 8) * LDPAD + k8 + tig];
                af[mt][2] = As[(rbase + gid) * LDPAD + k8 + tig + 4];
                af[mt][3] = As[(rbase + gid + 8) * LDPAD + k8 + tig + 4];
            }
            uint32_t bf[8][2];
#pragma unroll
            for (int ntl = 0; ntl < 8; ntl++) {
                int col = wn * 64 + ntl * 8 + gid;
                bf[ntl][0] = Ws[col * LDPAD + k8 + tig];
                bf[ntl][1] = Ws[col * LDPAD + k8 + tig + 4];
            }
#pragma unroll
            for (int mt = 0; mt < 2; mt++)
#pragma unroll
                for (int ntl = 0; ntl < 8; ntl++)
                    mma_tf32(acc[mt][ntl], af[mt], bf[ntl]);
        }
    }

#pragma unroll
    for (int mt = 0; mt < 2; mt++) {
        int row0 = m0 + wm * 32 + mt * 16 + gid;
        int row1 = row0 + 8;
#pragma unroll
        for (int ntl = 0; ntl < 8; ntl++) {
            int col = n0 + wn * 64 + ntl * 8 + tig * 2;
            float bx = 0.f, by = 0.f;
            if (bias) { bx = bias[col]; by = bias[col + 1]; }
            float2 v0 = make_float2(acc[mt][ntl][0] + bx, acc[mt][ntl][1] + by);
            float2 v1 = make_float2(acc[mt][ntl][2] + bx, acc[mt][ntl][3] + by);
            if (doRelu) {
                v0.x = fmaxf(v0.x, 0.f); v0.y = fmaxf(v0.y, 0.f);
                v1.x = fmaxf(v1.x, 0.f); v1.y = fmaxf(v1.y, 0.f);
            }
            if (row0 < M) *(float2*)(C + (size_t)row0 * Nout + col) = v0;
            if (row1 < M) *(float2*)(C + (size_t)row1 * Nout + col) = v1;
        }
    }
}

// -----------------------------------------------------------------------------
extern "C" void kernel_launch(void* const* d_in, const int* in_sizes, int n_in,
                              void* d_out, int out_size) {
    const float* x     = (const float*)d_in[0];
    const void*  ei    = d_in[1];
    const float* ew    = (const float*)d_in[2];
    const float* W1    = (const float*)d_in[3];
    const float* b1    = (const float*)d_in[4];
    const float* W2    = (const float*)d_in[5];
    const float* b2    = (const float*)d_in[6];
    const float* gamma = (const float*)d_in[7];
    const float* beta  = (const float*)d_in[8];
    float*       out   = (float*)d_out;

    float *dinv, *agg1, *h, *p;
    int *src, *dst, *cnt, *rowstart, *cursor;
    int2 *csr;
    cudaGetSymbolAddress((void**)&dinv,     g_dinv);
    cudaGetSymbolAddress((void**)&agg1,     g_agg1);
    cudaGetSymbolAddress((void**)&h,        g_h);
    cudaGetSymbolAddress((void**)&p,        g_p);
    cudaGetSymbolAddress((void**)&src,      g_src);
    cudaGetSymbolAddress((void**)&dst,      g_dst);
    cudaGetSymbolAddress((void**)&cnt,      g_count);
    cudaGetSymbolAddress((void**)&rowstart, g_rowstart);
    cudaGetSymbolAddress((void**)&cursor,   g_cursor);
    cudaGetSymbolAddress((void**)&csr,      g_csr);

    const int n = NN, e = EE;

    // 0. sniff dtype; zero deg + count
    detect_idx_kernel<<<1, 128>>>((const int*)ei);
    cudaMemsetAsync(dinv, 0, n * sizeof(float));
    cudaMemsetAsync(cnt,  0, n * sizeof(int));

    // 1. convert + weighted degree + counts; dinv; CSR build
    convert_deg_kernel<<<(e + 255) / 256, 256>>>(ei, ew, src, dst, dinv, cnt, e);
    dinv_kernel<<<(n + 255) / 256, 256>>>(dinv, n);
    scan_kernel<<<1, SCAN_T>>>(cnt, rowstart, cursor, n);
    csr_fill_kernel<<<(e + 255) / 256, 256>>>(src, dst, ew, dinv, cursor, csr, e);

    // 2. agg1 = A_norm @ x   (atomic-free gather, self-loop folded in)
    gather_kernel<0><<<(n * 32 + 255) / 256, 256>>>(rowstart, csr, dinv, x,
                                                    nullptr, nullptr, nullptr,
                                                    agg1, n);

    // 3. h = relu(agg1 @ W1^T + b1)
    {
        dim3 grid((n + 127) / 128, DH / 128);
        gemm_tf32_kernel<<<grid, 256>>>(agg1, W1, b1, h, n, DIN, DH, 1);
    }

    // 4. p = h @ W2^T (bias deferred to fused LN)
    {
        dim3 grid((n + 127) / 128, DIN / 128);
        gemm_tf32_kernel<<<grid, 256>>>(h, W2, nullptr, p, n, DH, DIN, 0);
    }

    // 5. out = LN(A_norm @ p + b2) * gamma + beta   (gather + LN fused)
    gather_kernel<1><<<(n * 32 + 255) / 256, 256>>>(rowstart, csr, dinv, p,
                                                    b2, gamma, beta, out, n);
}

// round 6
// speedup vs baseline: 1.9013x; 1.9013x over previous
#include <cuda_runtime.h>
#include <cstdint>
#include <cstddef>

#define NN   50000
#define EE   800000
#define DIN  128
#define DH   256
#define NBLK ((NN + 255) / 256)   // 196 scan blocks

// ---------------- scratch (device globals; no allocation allowed) ------------
__device__ float g_dinv[NN];             // weighted in-degree -> rsqrt in place
__device__ int   g_count[NN];            // per-dst edge count
__device__ int   g_rowstart[NN + 1];     // CSR offsets
__device__ int   g_cursor[NN];           // fill cursors (copy of offsets)
__device__ int   g_blocksum[NBLK + 1];   // scan block partials
__device__ int2  g_csr[EE];              // packed (src, nrm-as-bits) per slot
__device__ float g_agg1[NN * DIN];       // A @ x
__device__ float g_h[(size_t)NN * DH];   // relu(agg1 @ W1^T + b1)
__device__ float g_p[NN * DIN];          // h @ W2^T
__device__ int   g_src[EE];              // clean int32 src ids
__device__ int   g_dst[EE];              // clean int32 dst ids
__device__ int   g_is64;

// ---------------- dtype sniffer ----------------------------------------------
__global__ void detect_idx_kernel(const int* __restrict__ raw) {
    __shared__ int nz;
    if (threadIdx.x == 0) nz = 0;
    __syncthreads();
    if (raw[2 * threadIdx.x + 1] != 0) atomicOr(&nz, 1);
    __syncthreads();
    if (threadIdx.x == 0) g_is64 = (nz == 0) ? 1 : 0;
}

// ------- convert indices + weighted in-degree + per-dst edge counts ----------
__global__ void convert_deg_kernel(const void* __restrict__ raw,
                                   const float* __restrict__ w,
                                   int* __restrict__ src,
                                   int* __restrict__ dst,
                                   float* __restrict__ deg,
                                   int* __restrict__ cnt, int e) {
    int i = blockIdx.x * blockDim.x + threadIdx.x;
    if (i >= e) return;
    int s, d;
    if (g_is64) {
        const long long* p = (const long long*)raw;
        s = (int)p[i];
        d = (int)p[(size_t)e + i];
    } else {
        const int* p = (const int*)raw;
        s = p[i];
        d = p[e + i];
    }
    src[i] = s;
    dst[i] = d;
    atomicAdd(&deg[d], w[i]);
    atomicAdd(&cnt[d], 1);
}

__global__ void dinv_kernel(float* deg, int n) {
    int i = blockIdx.x * blockDim.x + threadIdx.x;
    if (i < n) deg[i] = rsqrtf(deg[i] + 1.0f);   // +1 = self-loop weight
}

// ---------------- device-wide exclusive scan (3 passes) ----------------------
// helper: inclusive block scan over 256 threads, returns inclusive value
__device__ __forceinline__ int block_scan_incl(int v) {
    const int lane = threadIdx.x & 31;
    const int warp = threadIdx.x >> 5;
    int s = v;
#pragma unroll
    for (int o = 1; o < 32; o <<= 1) {
        int t = __shfl_up_sync(0xFFFFFFFFu, s, o);
        if (lane >= o) s += t;
    }
    __shared__ int wsum[8];
    if (lane == 31) wsum[warp] = s;
    __syncthreads();
    if (warp == 0 && lane < 8) {
        int ws = wsum[lane];
#pragma unroll
        for (int o = 1; o < 8; o <<= 1) {
            int t = __shfl_up_sync(0xFFu, ws, o);
            if (lane >= o) ws += t;
        }
        wsum[lane] = ws;
    }
    __syncthreads();
    return s + (warp > 0 ? wsum[warp - 1] : 0);
}

// pass 1: per-block exclusive scan (block-local) + block sums
__global__ void scan_local_kernel(const int* __restrict__ cnt,
                                  int* __restrict__ rowstart,
                                  int* __restrict__ blocksum, int n) {
    int idx = blockIdx.x * 256 + threadIdx.x;
    int v = (idx < n) ? cnt[idx] : 0;
    int incl = block_scan_incl(v);
    if (idx < n) rowstart[idx] = incl - v;
    if (threadIdx.x == 255) blocksum[blockIdx.x] = incl;
}

// pass 2: single-block exclusive scan of block sums (nb <= 256), total at [nb]
__global__ void scan_block_kernel(int* __restrict__ blocksum, int nb) {
    int t = threadIdx.x;
    int v = (t < nb) ? blocksum[t] : 0;
    int incl = block_scan_incl(v);
    if (t < nb) blocksum[t] = incl - v;
    if (t == nb - 1) blocksum[nb] = incl;
}

// pass 3: add block offsets, fill cursor, set rowstart[n]
__global__ void scan_add_kernel(int* __restrict__ rowstart,
                                int* __restrict__ cursor,
                                const int* __restrict__ blocksum,
                                int n, int nb) {
    int idx = blockIdx.x * 256 + threadIdx.x;
    if (idx < n) {
        int r = rowstart[idx] + blocksum[blockIdx.x];
        rowstart[idx] = r;
        cursor[idx]   = r;
    }
    if (idx == 0) rowstart[n] = blocksum[nb];
}

// ---------------- CSR fill: slot <- (src, norm) ------------------------------
__global__ void csr_fill_kernel(const int* __restrict__ src,
                                const int* __restrict__ dst,
                                const float* __restrict__ w,
                                const float* __restrict__ dinv,
                                int* __restrict__ cursor,
                                int2* __restrict__ csr, int e) {
    int i = blockIdx.x * blockDim.x + threadIdx.x;
    if (i >= e) return;
    int s = src[i], d = dst[i];
    float nrm = dinv[s] * w[i] * dinv[d];
    int pos = atomicAdd(&cursor[d], 1);
    csr[pos] = make_int2(s, __float_as_int(nrm));
}

// ---------------- CSR gather: one warp per node, optional fused LN -----------
template <int DO_LN>
__global__ __launch_bounds__(256)
void gather_kernel(const int* __restrict__ rowstart,
                   const int2* __restrict__ csr,
                   const float* __restrict__ dinv,
                   const float* __restrict__ feat,
                   const float* __restrict__ b2,
                   const float* __restrict__ gamma,
                   const float* __restrict__ beta,
                   float* __restrict__ outb, int n) {
    const int node = (blockIdx.x * blockDim.x + threadIdx.x) >> 5;
    const int lane = threadIdx.x & 31;
    if (node >= n) return;

    float dv = dinv[node];
    float4 acc = *(const float4*)(feat + (size_t)node * DIN + lane * 4);
    acc.x *= dv * dv; acc.y *= dv * dv; acc.z *= dv * dv; acc.w *= dv * dv;

    const int beg = rowstart[node];
    const int end = rowstart[node + 1];

    int j = beg;
    for (; j + 1 < end; j += 2) {
        int2 e0 = csr[j];
        int2 e1 = csr[j + 1];
        const float4 v0 = *(const float4*)(feat + (size_t)e0.x * DIN + lane * 4);
        const float4 v1 = *(const float4*)(feat + (size_t)e1.x * DIN + lane * 4);
        float n0 = __int_as_float(e0.y), n1 = __int_as_float(e1.y);
        acc.x = fmaf(v0.x, n0, acc.x); acc.y = fmaf(v0.y, n0, acc.y);
        acc.z = fmaf(v0.z, n0, acc.z); acc.w = fmaf(v0.w, n0, acc.w);
        acc.x = fmaf(v1.x, n1, acc.x); acc.y = fmaf(v1.y, n1, acc.y);
        acc.z = fmaf(v1.z, n1, acc.z); acc.w = fmaf(v1.w, n1, acc.w);
    }
    if (j < end) {
        int2 e0 = csr[j];
        const float4 v0 = *(const float4*)(feat + (size_t)e0.x * DIN + lane * 4);
        float n0 = __int_as_float(e0.y);
        acc.x = fmaf(v0.x, n0, acc.x); acc.y = fmaf(v0.y, n0, acc.y);
        acc.z = fmaf(v0.z, n0, acc.z); acc.w = fmaf(v0.w, n0, acc.w);
    }

    if (DO_LN) {
        float4 bb = *(const float4*)(b2 + lane * 4);
        acc.x += bb.x; acc.y += bb.y; acc.z += bb.z; acc.w += bb.w;

        float s = acc.x + acc.y + acc.z + acc.w;
#pragma unroll
        for (int o = 16; o > 0; o >>= 1) s += __shfl_xor_sync(0xFFFFFFFFu, s, o);
        float mu = s * (1.0f / DIN);

        float dx = acc.x - mu, dy = acc.y - mu, dz = acc.z - mu, dw = acc.w - mu;
        float q = dx * dx + dy * dy + dz * dz + dw * dw;
#pragma unroll
        for (int o = 16; o > 0; o >>= 1) q += __shfl_xor_sync(0xFFFFFFFFu, q, o);
        float rstd = rsqrtf(q * (1.0f / DIN) + 1e-5f);

        float4 g  = *(const float4*)(gamma + lane * 4);
        float4 bt = *(const float4*)(beta + lane * 4);
        float4 o4;
        o4.x = dx * rstd * g.x + bt.x;
        o4.y = dy * rstd * g.y + bt.y;
        o4.z = dz * rstd * g.z + bt.z;
        o4.w = dw * rstd * g.w + bt.w;
        *(float4*)(outb + (size_t)node * DIN + lane * 4) = o4;
    } else {
        *(float4*)(outb + (size_t)node * DIN + lane * 4) = acc;
    }
}

// ---------------- TF32 tensor-core GEMM --------------------------------------
__device__ __forceinline__ uint32_t f2tf32(float f) {
    uint32_t u;
    asm("cvt.rna.tf32.f32 %0, %1;" : "=r"(u) : "f"(f));
    return u;
}

__device__ __forceinline__ void mma_tf32(float c[4], const uint32_t a[4],
                                         const uint32_t b[2]) {
    asm volatile(
        "mma.sync.aligned.m16n8k8.row.col.f32.tf32.tf32.f32 "
        "{%0,%1,%2,%3}, {%4,%5,%6,%7}, {%8,%9}, {%0,%1,%2,%3};"
        : "+f"(c[0]), "+f"(c[1]), "+f"(c[2]), "+f"(c[3])
        : "r"(a[0]), "r"(a[1]), "r"(a[2]), "r"(a[3]), "r"(b[0]), "r"(b[1]));
}

#define LDPAD 36

__global__ __launch_bounds__(256)
void gemm_tf32_kernel(const float* __restrict__ A, const float* __restrict__ W,
                      const float* __restrict__ bias, float* __restrict__ C,
                      int M, int K, int Nout, int doRelu) {
    __shared__ uint32_t As[128 * LDPAD];
    __shared__ uint32_t Ws[128 * LDPAD];

    const int tid  = threadIdx.x;
    const int lane = tid & 31;
    const int warp = tid >> 5;
    const int wm   = warp & 3;
    const int wn   = warp >> 2;
    const int gid  = lane >> 2;
    const int tig  = lane & 3;
    const int m0   = blockIdx.x * 128;
    const int n0   = blockIdx.y * 128;

    const int lrow = tid >> 3;
    const int lkq  = tid & 7;

    float acc[2][8][4];
#pragma unroll
    for (int i = 0; i < 2; i++)
#pragma unroll
        for (int j = 0; j < 8; j++)
#pragma unroll
            for (int q = 0; q < 4; q++) acc[i][j][q] = 0.f;

    const int nt = K / 32;
    for (int kt = 0; kt < nt; kt++) {
        const int kbase = kt * 32;
        float4 av[4], wv[4];
#pragma unroll
        for (int l = 0; l < 4; l++) {
            int row = lrow + l * 32;
            av[l] = (m0 + row < M)
                  ? *(const float4*)(A + (size_t)(m0 + row) * K + kbase + lkq * 4)
                  : make_float4(0.f, 0.f, 0.f, 0.f);
            wv[l] = *(const float4*)(W + (size_t)(n0 + row) * K + kbase + lkq * 4);
        }
        if (kt > 0) __syncthreads();
#pragma unroll
        for (int l = 0; l < 4; l++) {
            int row = lrow + l * 32;
            uint4 ua = make_uint4(f2tf32(av[l].x), f2tf32(av[l].y),
                                  f2tf32(av[l].z), f2tf32(av[l].w));
            uint4 uw = make_uint4(f2tf32(wv[l].x), f2tf32(wv[l].y),
                                  f2tf32(wv[l].z), f2tf32(wv[l].w));
            *(uint4*)&As[row * LDPAD + lkq * 4] = ua;
            *(uint4*)&Ws[row * LDPAD + lkq * 4] = uw;
        }
        __syncthreads();

#pragma unroll
        for (int ks = 0; ks < 4; ks++) {
            const int k8 = ks * 8;
            uint32_t af[2][4];
#pragma unroll
            for (int mt = 0; mt < 2; mt++) {
                int rbase = wm * 32 + mt * 16;
                af[mt][0] = As[(rbase + gid) * LDPAD + k8 + tig];
                af[mt][1] = As[(rbase + gid + 8) * LDPAD + k8 + tig];
                af[mt][2] = As[(rbase + gid) * LDPAD + k8 + tig + 4];
                af[mt][3] = As[(rbase + gid + 8) * LDPAD + k8 + tig + 4];
            }
            uint32_t bf[8][2];
#pragma unroll
            for (int ntl = 0; ntl < 8; ntl++) {
                int col = wn * 64 + ntl * 8 + gid;
                bf[ntl][0] = Ws[col * LDPAD + k8 + tig];
                bf[ntl][1] = Ws[col * LDPAD + k8 + tig + 4];
            }
#pragma unroll
            for (int mt = 0; mt < 2; mt++)
#pragma unroll
                for (int ntl = 0; ntl < 8; ntl++)
                    mma_tf32(acc[mt][ntl], af[mt], bf[ntl]);
        }
    }

#pragma unroll
    for (int mt = 0; mt < 2; mt++) {
        int row0 = m0 + wm * 32 + mt * 16 + gid;
        int row1 = row0 + 8;
#pragma unroll
        for (int ntl = 0; ntl < 8; ntl++) {
            int col = n0 + wn * 64 + ntl * 8 + tig * 2;
            float bx = 0.f, by = 0.f;
            if (bias) { bx = bias[col]; by = bias[col + 1]; }
            float2 v0 = make_float2(acc[mt][ntl][0] + bx, acc[mt][ntl][1] + by);
            float2 v1 = make_float2(acc[mt][ntl][2] + bx, acc[mt][ntl][3] + by);
            if (doRelu) {
                v0.x = fmaxf(v0.x, 0.f); v0.y = fmaxf(v0.y, 0.f);
                v1.x = fmaxf(v1.x, 0.f); v1.y = fmaxf(v1.y, 0.f);
            }
            if (row0 < M) *(float2*)(C + (size_t)row0 * Nout + col) = v0;
            if (row1 < M) *(float2*)(C + (size_t)row1 * Nout + col) = v1;
        }
    }
}

// -----------------------------------------------------------------------------
extern "C" void kernel_launch(void* const* d_in, const int* in_sizes, int n_in,
                              void* d_out, int out_size) {
    const float* x     = (const float*)d_in[0];
    const void*  ei    = d_in[1];
    const float* ew    = (const float*)d_in[2];
    const float* W1    = (const float*)d_in[3];
    const float* b1    = (const float*)d_in[4];
    const float* W2    = (const float*)d_in[5];
    const float* b2    = (const float*)d_in[6];
    const float* gamma = (const float*)d_in[7];
    const float* beta  = (const float*)d_in[8];
    float*       out   = (float*)d_out;

    float *dinv, *agg1, *h, *p;
    int *src, *dst, *cnt, *rowstart, *cursor, *blocksum;
    int2 *csr;
    cudaGetSymbolAddress((void**)&dinv,     g_dinv);
    cudaGetSymbolAddress((void**)&agg1,     g_agg1);
    cudaGetSymbolAddress((void**)&h,        g_h);
    cudaGetSymbolAddress((void**)&p,        g_p);
    cudaGetSymbolAddress((void**)&src,      g_src);
    cudaGetSymbolAddress((void**)&dst,      g_dst);
    cudaGetSymbolAddress((void**)&cnt,      g_count);
    cudaGetSymbolAddress((void**)&rowstart, g_rowstart);
    cudaGetSymbolAddress((void**)&cursor,   g_cursor);
    cudaGetSymbolAddress((void**)&blocksum, g_blocksum);
    cudaGetSymbolAddress((void**)&csr,      g_csr);

    const int n = NN, e = EE;

    // 0. sniff dtype; zero deg + count
    detect_idx_kernel<<<1, 128>>>((const int*)ei);
    cudaMemsetAsync(dinv, 0, n * sizeof(float));
    cudaMemsetAsync(cnt,  0, n * sizeof(int));

    // 1. convert + weighted degree + counts; dinv; CSR build (3-pass scan)
    convert_deg_kernel<<<(e + 255) / 256, 256>>>(ei, ew, src, dst, dinv, cnt, e);
    dinv_kernel<<<(n + 255) / 256, 256>>>(dinv, n);
    scan_local_kernel<<<NBLK, 256>>>(cnt, rowstart, blocksum, n);
    scan_block_kernel<<<1, 256>>>(blocksum, NBLK);
    scan_add_kernel<<<NBLK, 256>>>(rowstart, cursor, blocksum, n, NBLK);
    csr_fill_kernel<<<(e + 255) / 256, 256>>>(src, dst, ew, dinv, cursor, csr, e);

    // 2. agg1 = A_norm @ x   (atomic-free gather, self-loop folded in)
    gather_kernel<0><<<(n * 32 + 255) / 256, 256>>>(rowstart, csr, dinv, x,
                                                    nullptr, nullptr, nullptr,
                                                    agg1, n);

    // 3. h = relu(agg1 @ W1^T + b1)
    {
        dim3 grid((n + 127) / 128, DH / 128);
        gemm_tf32_kernel<<<grid, 256>>>(agg1, W1, b1, h, n, DIN, DH, 1);
    }

    // 4. p = h @ W2^T (bias deferred to fused LN)
    {
        dim3 grid((n + 127) / 128, DIN / 128);
        gemm_tf32_kernel<<<grid, 256>>>(h, W2, nullptr, p, n, DH, DIN, 0);
    }

    // 5. out = LN(A_norm @ p + b2) * gamma + beta   (gather + LN fused)
    gather_kernel<1><<<(n * 32 + 255) / 256, 256>>>(rowstart, csr, dinv, p,
                                                    b2, gamma, beta, out, n);
}

// round 7
// speedup vs baseline: 1.9524x; 1.0268x over previous
#include <cuda_runtime.h>
#include <cuda_fp16.h>
#include <cstdint>
#include <cstddef>

#define NN   50000
#define EE   800000
#define DIN  128
#define DH   256
#define NBLK ((NN + 255) / 256)   // 196 scan blocks

// ---------------- scratch (device globals; no allocation allowed) ------------
__device__ float  g_dinv[NN];             // weighted in-degree -> rsqrt in place
__device__ int    g_count[NN];            // per-dst edge count
__device__ int    g_rowstart[NN + 1];     // CSR offsets
__device__ int    g_cursor[NN];           // fill cursors
__device__ int    g_blocksum[NBLK + 1];   // scan block partials
__device__ int2   g_csr[EE];              // packed (src, nrm-as-bits)
__device__ __half g_xh[NN * DIN];         // x in fp16
__device__ float  g_agg1[NN * DIN];       // A @ x  (fp32, GEMM1 input)
__device__ float  g_h[(size_t)NN * DH];   // relu(agg1 @ W1^T + b1)
__device__ __half g_ph[NN * DIN];         // h @ W2^T in fp16
__device__ int    g_src[EE];
__device__ int    g_dst[EE];
__device__ int    g_is64;

// ---------------- dtype sniffer ----------------------------------------------
__global__ void detect_idx_kernel(const int* __restrict__ raw) {
    __shared__ int nz;
    if (threadIdx.x == 0) nz = 0;
    __syncthreads();
    if (raw[2 * threadIdx.x + 1] != 0) atomicOr(&nz, 1);
    __syncthreads();
    if (threadIdx.x == 0) g_is64 = (nz == 0) ? 1 : 0;
}

// ---------------- fp32 -> fp16 feature conversion ----------------------------
__global__ void f2h_kernel(const float* __restrict__ in,
                           __half* __restrict__ outp, int pairs) {
    int i = blockIdx.x * blockDim.x + threadIdx.x;
    if (i < pairs) {
        float2 v = ((const float2*)in)[i];
        ((__half2*)outp)[i] = __floats2half2_rn(v.x, v.y);
    }
}

// ------- convert indices + weighted in-degree + per-dst edge counts ----------
__global__ void convert_deg_kernel(const void* __restrict__ raw,
                                   const float* __restrict__ w,
                                   int* __restrict__ src,
                                   int* __restrict__ dst,
                                   float* __restrict__ deg,
                                   int* __restrict__ cnt, int e) {
    int i = blockIdx.x * blockDim.x + threadIdx.x;
    if (i >= e) return;
    int s, d;
    if (g_is64) {
        const long long* p = (const long long*)raw;
        s = (int)p[i];
        d = (int)p[(size_t)e + i];
    } else {
        const int* p = (const int*)raw;
        s = p[i];
        d = p[e + i];
    }
    src[i] = s;
    dst[i] = d;
    atomicAdd(&deg[d], w[i]);
    atomicAdd(&cnt[d], 1);
}

__global__ void dinv_kernel(float* deg, int n) {
    int i = blockIdx.x * blockDim.x + threadIdx.x;
    if (i < n) deg[i] = rsqrtf(deg[i] + 1.0f);   // +1 = self-loop weight
}

// ---------------- device-wide exclusive scan (3 passes) ----------------------
__device__ __forceinline__ int block_scan_incl(int v) {
    const int lane = threadIdx.x & 31;
    const int warp = threadIdx.x >> 5;
    int s = v;
#pragma unroll
    for (int o = 1; o < 32; o <<= 1) {
        int t = __shfl_up_sync(0xFFFFFFFFu, s, o);
        if (lane >= o) s += t;
    }
    __shared__ int wsum[8];
    if (lane == 31) wsum[warp] = s;
    __syncthreads();
    if (warp == 0 && lane < 8) {
        int ws = wsum[lane];
#pragma unroll
        for (int o = 1; o < 8; o <<= 1) {
            int t = __shfl_up_sync(0xFFu, ws, o);
            if (lane >= o) ws += t;
        }
        wsum[lane] = ws;
    }
    __syncthreads();
    return s + (warp > 0 ? wsum[warp - 1] : 0);
}

__global__ void scan_local_kernel(const int* __restrict__ cnt,
                                  int* __restrict__ rowstart,
                                  int* __restrict__ blocksum, int n) {
    int idx = blockIdx.x * 256 + threadIdx.x;
    int v = (idx < n) ? cnt[idx] : 0;
    int incl = block_scan_incl(v);
    if (idx < n) rowstart[idx] = incl - v;
    if (threadIdx.x == 255) blocksum[blockIdx.x] = incl;
}

__global__ void scan_block_kernel(int* __restrict__ blocksum, int nb) {
    int t = threadIdx.x;
    int v = (t < nb) ? blocksum[t] : 0;
    int incl = block_scan_incl(v);
    if (t < nb) blocksum[t] = incl - v;
    if (t == nb - 1) blocksum[nb] = incl;
}

__global__ void scan_add_kernel(int* __restrict__ rowstart,
                                int* __restrict__ cursor,
                                const int* __restrict__ blocksum,
                                int n, int nb) {
    int idx = blockIdx.x * 256 + threadIdx.x;
    if (idx < n) {
        int r = rowstart[idx] + blocksum[blockIdx.x];
        rowstart[idx] = r;
        cursor[idx]   = r;
    }
    if (idx == 0) rowstart[n] = blocksum[nb];
}

// ---------------- CSR fill: slot <- (src, norm) ------------------------------
__global__ void csr_fill_kernel(const int* __restrict__ src,
                                const int* __restrict__ dst,
                                const float* __restrict__ w,
                                const float* __restrict__ dinv,
                                int* __restrict__ cursor,
                                int2* __restrict__ csr, int e) {
    int i = blockIdx.x * blockDim.x + threadIdx.x;
    if (i >= e) return;
    int s = src[i], d = dst[i];
    float nrm = dinv[s] * w[i] * dinv[d];
    int pos = atomicAdd(&cursor[d], 1);
    csr[pos] = make_int2(s, __float_as_int(nrm));
}

// ---------------- CSR gather over fp16 features, fp32 accumulate -------------
// one warp per node; lane covers 4 features (half4 = uint2 load).
__device__ __forceinline__ float4 h4_to_f4(uint2 u) {
    __half2 a = *(__half2*)&u.x;
    __half2 b = *(__half2*)&u.y;
    float2 fa = __half22float2(a);
    float2 fb = __half22float2(b);
    return make_float4(fa.x, fa.y, fb.x, fb.y);
}

template <int DO_LN>
__global__ __launch_bounds__(256)
void gather_kernel(const int* __restrict__ rowstart,
                   const int2* __restrict__ csr,
                   const float* __restrict__ dinv,
                   const __half* __restrict__ feat,
                   const float* __restrict__ b2,
                   const float* __restrict__ gamma,
                   const float* __restrict__ beta,
                   float* __restrict__ outb, int n) {
    const int node = (blockIdx.x * blockDim.x + threadIdx.x) >> 5;
    const int lane = threadIdx.x & 31;
    if (node >= n) return;

    const uint2* fp = (const uint2*)feat;   // 16 uint2 per row... row = 32 uint2
    // row stride in uint2 units: DIN/4 = 32
    float dv = dinv[node];
    float4 acc = h4_to_f4(fp[node * 32 + lane]);
    acc.x *= dv * dv; acc.y *= dv * dv; acc.z *= dv * dv; acc.w *= dv * dv;

    const int beg = rowstart[node];
    const int end = rowstart[node + 1];

    int j = beg;
    // 4x batched: issue 4 independent row loads, then FMA
    for (; j + 3 < end; j += 4) {
        int2 e0 = csr[j], e1 = csr[j + 1], e2 = csr[j + 2], e3 = csr[j + 3];
        uint2 r0 = fp[e0.x * 32 + lane];
        uint2 r1 = fp[e1.x * 32 + lane];
        uint2 r2 = fp[e2.x * 32 + lane];
        uint2 r3 = fp[e3.x * 32 + lane];
        float4 v0 = h4_to_f4(r0), v1 = h4_to_f4(r1);
        float4 v2 = h4_to_f4(r2), v3 = h4_to_f4(r3);
        float n0 = __int_as_float(e0.y), n1 = __int_as_float(e1.y);
        float n2 = __int_as_float(e2.y), n3 = __int_as_float(e3.y);
        acc.x = fmaf(v0.x, n0, acc.x); acc.y = fmaf(v0.y, n0, acc.y);
        acc.z = fmaf(v0.z, n0, acc.z); acc.w = fmaf(v0.w, n0, acc.w);
        acc.x = fmaf(v1.x, n1, acc.x); acc.y = fmaf(v1.y, n1, acc.y);
        acc.z = fmaf(v1.z, n1, acc.z); acc.w = fmaf(v1.w, n1, acc.w);
        acc.x = fmaf(v2.x, n2, acc.x); acc.y = fmaf(v2.y, n2, acc.y);
        acc.z = fmaf(v2.z, n2, acc.z); acc.w = fmaf(v2.w, n2, acc.w);
        acc.x = fmaf(v3.x, n3, acc.x); acc.y = fmaf(v3.y, n3, acc.y);
        acc.z = fmaf(v3.z, n3, acc.z); acc.w = fmaf(v3.w, n3, acc.w);
    }
    for (; j < end; j++) {
        int2 e0 = csr[j];
        float4 v0 = h4_to_f4(fp[e0.x * 32 + lane]);
        float n0 = __int_as_float(e0.y);
        acc.x = fmaf(v0.x, n0, acc.x); acc.y = fmaf(v0.y, n0, acc.y);
        acc.z = fmaf(v0.z, n0, acc.z); acc.w = fmaf(v0.w, n0, acc.w);
    }

    if (DO_LN) {
        float4 bb = *(const float4*)(b2 + lane * 4);
        acc.x += bb.x; acc.y += bb.y; acc.z += bb.z; acc.w += bb.w;

        float s = acc.x + acc.y + acc.z + acc.w;
#pragma unroll
        for (int o = 16; o > 0; o >>= 1) s += __shfl_xor_sync(0xFFFFFFFFu, s, o);
        float mu = s * (1.0f / DIN);

        float dx = acc.x - mu, dy = acc.y - mu, dz = acc.z - mu, dw = acc.w - mu;
        float q = dx * dx + dy * dy + dz * dz + dw * dw;
#pragma unroll
        for (int o = 16; o > 0; o >>= 1) q += __shfl_xor_sync(0xFFFFFFFFu, q, o);
        float rstd = rsqrtf(q * (1.0f / DIN) + 1e-5f);

        float4 g  = *(const float4*)(gamma + lane * 4);
        float4 bt = *(const float4*)(beta + lane * 4);
        float4 o4;
        o4.x = dx * rstd * g.x + bt.x;
        o4.y = dy * rstd * g.y + bt.y;
        o4.z = dz * rstd * g.z + bt.z;
        o4.w = dw * rstd * g.w + bt.w;
        *(float4*)(outb + (size_t)node * DIN + lane * 4) = o4;
    } else {
        *(float4*)(outb + (size_t)node * DIN + lane * 4) = acc;
    }
}

// ---------------- TF32 tensor-core GEMM --------------------------------------
__device__ __forceinline__ uint32_t f2tf32(float f) {
    uint32_t u;
    asm("cvt.rna.tf32.f32 %0, %1;" : "=r"(u) : "f"(f));
    return u;
}

__device__ __forceinline__ void mma_tf32(float c[4], const uint32_t a[4],
                                         const uint32_t b[2]) {
    asm volatile(
        "mma.sync.aligned.m16n8k8.row.col.f32.tf32.tf32.f32 "
        "{%0,%1,%2,%3}, {%4,%5,%6,%7}, {%8,%9}, {%0,%1,%2,%3};"
        : "+f"(c[0]), "+f"(c[1]), "+f"(c[2]), "+f"(c[3])
        : "r"(a[0]), "r"(a[1]), "r"(a[2]), "r"(a[3]), "r"(b[0]), "r"(b[1]));
}

#define LDPAD 36

// OUT_HALF=1 -> C is __half (written as half2); else float (float2)
template <int OUT_HALF>
__global__ __launch_bounds__(256)
void gemm_tf32_kernel(const float* __restrict__ A, const float* __restrict__ W,
                      const float* __restrict__ bias, void* __restrict__ Cv,
                      int M, int K, int Nout, int doRelu) {
    __shared__ uint32_t As[128 * LDPAD];
    __shared__ uint32_t Ws[128 * LDPAD];

    const int tid  = threadIdx.x;
    const int lane = tid & 31;
    const int warp = tid >> 5;
    const int wm   = warp & 3;
    const int wn   = warp >> 2;
    const int gid  = lane >> 2;
    const int tig  = lane & 3;
    const int m0   = blockIdx.x * 128;
    const int n0   = blockIdx.y * 128;

    const int lrow = tid >> 3;
    const int lkq  = tid & 7;

    float acc[2][8][4];
#pragma unroll
    for (int i = 0; i < 2; i++)
#pragma unroll
        for (int j = 0; j < 8; j++)
#pragma unroll
            for (int q = 0; q < 4; q++) acc[i][j][q] = 0.f;

    const int nt = K / 32;
    for (int kt = 0; kt < nt; kt++) {
        const int kbase = kt * 32;
        float4 av[4], wv[4];
#pragma unroll
        for (int l = 0; l < 4; l++) {
            int row = lrow + l * 32;
            av[l] = (m0 + row < M)
                  ? *(const float4*)(A + (size_t)(m0 + row) * K + kbase + lkq * 4)
                  : make_float4(0.f, 0.f, 0.f, 0.f);
            wv[l] = *(const float4*)(W + (size_t)(n0 + row) * K + kbase + lkq * 4);
        }
        if (kt > 0) __syncthreads();
#pragma unroll
        for (int l = 0; l < 4; l++) {
            int row = lrow + l * 32;
            uint4 ua = make_uint4(f2tf32(av[l].x), f2tf32(av[l].y),
                                  f2tf32(av[l].z), f2tf32(av[l].w));
            uint4 uw = make_uint4(f2tf32(wv[l].x), f2tf32(wv[l].y),
                                  f2tf32(wv[l].z), f2tf32(wv[l].w));
            *(uint4*)&As[row * LDPAD + lkq * 4] = ua;
            *(uint4*)&Ws[row * LDPAD + lkq * 4] = uw;
        }
        __syncthreads();

#pragma unroll
        for (int ks = 0; ks < 4; ks++) {
            const int k8 = ks * 8;
            uint32_t af[2][4];
#pragma unroll
            for (int mt = 0; mt < 2; mt++) {
                int rbase = wm * 32 + mt * 16;
                af[mt][0] = As[(rbase + gid) * LDPAD + k8 + tig];
                af[mt][1] = As[(rbase + gid + 8) * LDPAD + k8 + tig];
                af[mt][2] = As[(rbase + gid) * LDPAD + k8 + tig + 4];
                af[mt][3] = As[(rbase + gid + 8) * LDPAD + k8 + tig + 4];
            }
            uint32_t bf[8][2];
#pragma unroll
            for (int ntl = 0; ntl < 8; ntl++) {
                int col = wn * 64 + ntl * 8 + gid;
                bf[ntl][0] = Ws[col * LDPAD + k8 + tig];
                bf[ntl][1] = Ws[col * LDPAD + k8 + tig + 4];
            }
#pragma unroll
            for (int mt = 0; mt < 2; mt++)
#pragma unroll
                for (int ntl = 0; ntl < 8; ntl++)
                    mma_tf32(acc[mt][ntl], af[mt], bf[ntl]);
        }
    }

#pragma unroll
    for (int mt = 0; mt < 2; mt++) {
        int row0 = m0 + wm * 32 + mt * 16 + gid;
        int row1 = row0 + 8;
#pragma unroll
        for (int ntl = 0; ntl < 8; ntl++) {
            int col = n0 + wn * 64 + ntl * 8 + tig * 2;
            float bx = 0.f, by = 0.f;
            if (bias) { bx = bias[col]; by = bias[col + 1]; }
            float2 v0 = make_float2(acc[mt][ntl][0] + bx, acc[mt][ntl][1] + by);
            float2 v1 = make_float2(acc[mt][ntl][2] + bx, acc[mt][ntl][3] + by);
            if (doRelu) {
                v0.x = fmaxf(v0.x, 0.f); v0.y = fmaxf(v0.y, 0.f);
                v1.x = fmaxf(v1.x, 0.f); v1.y = fmaxf(v1.y, 0.f);
            }
            if (OUT_HALF) {
                __half2* C = (__half2*)Cv;
                if (row0 < M) C[((size_t)row0 * Nout + col) >> 1] = __floats2half2_rn(v0.x, v0.y);
                if (row1 < M) C[((size_t)row1 * Nout + col) >> 1] = __floats2half2_rn(v1.x, v1.y);
            } else {
                float* C = (float*)Cv;
                if (row0 < M) *(float2*)(C + (size_t)row0 * Nout + col) = v0;
                if (row1 < M) *(float2*)(C + (size_t)row1 * Nout + col) = v1;
            }
        }
    }
}

// -----------------------------------------------------------------------------
extern "C" void kernel_launch(void* const* d_in, const int* in_sizes, int n_in,
                              void* d_out, int out_size) {
    const float* x     = (const float*)d_in[0];
    const void*  ei    = d_in[1];
    const float* ew    = (const float*)d_in[2];
    const float* W1    = (const float*)d_in[3];
    const float* b1    = (const float*)d_in[4];
    const float* W2    = (const float*)d_in[5];
    const float* b2    = (const float*)d_in[6];
    const float* gamma = (const float*)d_in[7];
    const float* beta  = (const float*)d_in[8];
    float*       out   = (float*)d_out;

    float *dinv, *agg1, *h;
    __half *xh, *ph;
    int *src, *dst, *cnt, *rowstart, *cursor, *blocksum;
    int2 *csr;
    cudaGetSymbolAddress((void**)&dinv,     g_dinv);
    cudaGetSymbolAddress((void**)&agg1,     g_agg1);
    cudaGetSymbolAddress((void**)&h,        g_h);
    cudaGetSymbolAddress((void**)&xh,       g_xh);
    cudaGetSymbolAddress((void**)&ph,       g_ph);
    cudaGetSymbolAddress((void**)&src,      g_src);
    cudaGetSymbolAddress((void**)&dst,      g_dst);
    cudaGetSymbolAddress((void**)&cnt,      g_count);
    cudaGetSymbolAddress((void**)&rowstart, g_rowstart);
    cudaGetSymbolAddress((void**)&cursor,   g_cursor);
    cudaGetSymbolAddress((void**)&blocksum, g_blocksum);
    cudaGetSymbolAddress((void**)&csr,      g_csr);

    const int n = NN, e = EE;

    // 0. sniff dtype; zero deg + count; convert x -> fp16
    detect_idx_kernel<<<1, 128>>>((const int*)ei);
    cudaMemsetAsync(dinv, 0, n * sizeof(float));
    cudaMemsetAsync(cnt,  0, n * sizeof(int));
    f2h_kernel<<<(n * DIN / 2 + 255) / 256, 256>>>(x, xh, n * DIN / 2);

    // 1. convert + weighted degree + counts; dinv; CSR build (3-pass scan)
    convert_deg_kernel<<<(e + 255) / 256, 256>>>(ei, ew, src, dst, dinv, cnt, e);
    dinv_kernel<<<(n + 255) / 256, 256>>>(dinv, n);
    scan_local_kernel<<<NBLK, 256>>>(cnt, rowstart, blocksum, n);
    scan_block_kernel<<<1, 256>>>(blocksum, NBLK);
    scan_add_kernel<<<NBLK, 256>>>(rowstart, cursor, blocksum, n, NBLK);
    csr_fill_kernel<<<(e + 255) / 256, 256>>>(src, dst, ew, dinv, cursor, csr, e);

    // 2. agg1 = A_norm @ x   (fp16 gather, fp32 accumulate)
    gather_kernel<0><<<(n * 32 + 255) / 256, 256>>>(rowstart, csr, dinv, xh,
                                                    nullptr, nullptr, nullptr,
                                                    agg1, n);

    // 3. h = relu(agg1 @ W1^T + b1)
    {
        dim3 grid((n + 127) / 128, DH / 128);
        gemm_tf32_kernel<0><<<grid, 256>>>(agg1, W1, b1, h, n, DIN, DH, 1);
    }

    // 4. p = h @ W2^T  -> fp16 (bias deferred to fused LN)
    {
        dim3 grid((n + 127) / 128, DIN / 128);
        gemm_tf32_kernel<1><<<grid, 256>>>(h, W2, nullptr, ph, n, DH, DIN, 0);
    }

    // 5. out = LN(A_norm @ p + b2) * gamma + beta   (fp16 gather + LN fused)
    gather_kernel<1><<<(n * 32 + 255) / 256, 256>>>(rowstart, csr, dinv, ph,
                                                    b2, gamma, beta, out, n);
}

// round 8
// speedup vs baseline: 1.9794x; 1.0138x over previous
#include <cuda_runtime.h>
#include <cuda_fp16.h>
#include <cstdint>
#include <cstddef>

#define NN   50000
#define EE   800000
#define DIN  128
#define DH   256
#define NBLK ((NN + 255) / 256)   // 196 scan blocks

// ---------------- scratch (device globals; no allocation allowed) ------------
__device__ float  g_dinv[NN];             // weighted in-degree -> rsqrt in place
__device__ int    g_count[NN];            // per-dst edge count
__device__ int    g_rowstart[NN + 1];     // CSR offsets
__device__ int    g_cursor[NN];           // fill cursors
__device__ int2   g_csr[EE];              // packed (src, nrm-as-bits)
__device__ __half g_xh[NN * DIN];         // x in fp16
__device__ float  g_agg1[NN * DIN];       // A @ x  (fp32, GEMM1 input)
__device__ float  g_h[(size_t)NN * DH];   // relu(agg1 @ W1^T + b1)
__device__ __half g_ph[NN * DIN];         // h @ W2^T in fp16
__device__ int    g_src[EE];
__device__ int    g_dst[EE];
__device__ int    g_is64;
__device__ int    g_ticket;                        // lookback ticket
__device__ unsigned long long g_state[NBLK];       // value<<2 | flag

// ---------------- prep: zero scratch + dtype detect + x -> fp16 --------------
__global__ void prep_kernel(const int* __restrict__ raw,
                            const float* __restrict__ x,
                            __half* __restrict__ xh,
                            float* __restrict__ deg,
                            int* __restrict__ cnt) {
    const int gtid   = blockIdx.x * blockDim.x + threadIdx.x;
    const int stride = gridDim.x * blockDim.x;

    for (int i = gtid; i < NN; i += stride) { deg[i] = 0.f; cnt[i] = 0; }
    for (int i = gtid; i < NBLK; i += stride) g_state[i] = 0ull;
    if (gtid == 0) g_ticket = 0;

    // x -> fp16 (half2 at a time)
    const int pairs = NN * DIN / 2;
    const float2* xin = (const float2*)x;
    __half2* xo = (__half2*)xh;
    for (int i = gtid; i < pairs; i += stride) {
        float2 v = xin[i];
        xo[i] = __floats2half2_rn(v.x, v.y);
    }

    // dtype detect (block 0): int64 little-endian -> odd words all zero
    if (blockIdx.x == 0) {
        int odd = (threadIdx.x < 128) ? raw[2 * threadIdx.x + 1] : 0;
        int any = __syncthreads_or(odd != 0);
        if (threadIdx.x == 0) g_is64 = any ? 0 : 1;
    }
}

// ------- convert indices + weighted in-degree + per-dst edge counts ----------
__global__ void convert_deg_kernel(const void* __restrict__ raw,
                                   const float* __restrict__ w,
                                   int* __restrict__ src,
                                   int* __restrict__ dst,
                                   float* __restrict__ deg,
                                   int* __restrict__ cnt, int e) {
    int i = blockIdx.x * blockDim.x + threadIdx.x;
    if (i >= e) return;
    int s, d;
    if (g_is64) {
        const long long* p = (const long long*)raw;
        s = (int)p[i];
        d = (int)p[(size_t)e + i];
    } else {
        const int* p = (const int*)raw;
        s = p[i];
        d = p[e + i];
    }
    src[i] = s;
    dst[i] = d;
    atomicAdd(&deg[d], w[i]);
    atomicAdd(&cnt[d], 1);
}

// ---------------- single-pass lookback scan (+dinv fused) --------------------
__device__ __forceinline__ int block_scan_incl(int v) {
    const int lane = threadIdx.x & 31;
    const int warp = threadIdx.x >> 5;
    int s = v;
#pragma unroll
    for (int o = 1; o < 32; o <<= 1) {
        int t = __shfl_up_sync(0xFFFFFFFFu, s, o);
        if (lane >= o) s += t;
    }
    __shared__ int wsum[8];
    if (lane == 31) wsum[warp] = s;
    __syncthreads();
    if (warp == 0 && lane < 8) {
        int ws = wsum[lane];
#pragma unroll
        for (int o = 1; o < 8; o <<= 1) {
            int t = __shfl_up_sync(0xFFu, ws, o);
            if (lane >= o) ws += t;
        }
        wsum[lane] = ws;
    }
    __syncthreads();
    return s + (warp > 0 ? wsum[warp - 1] : 0);
}

__global__ void scan_lookback_kernel(const int* __restrict__ cnt,
                                     float* __restrict__ deg,   // -> dinv
                                     int* __restrict__ rowstart,
                                     int* __restrict__ cursor, int n) {
    __shared__ int s_bid, s_total, s_excl;
    if (threadIdx.x == 0) s_bid = atomicAdd(&g_ticket, 1);
    __syncthreads();
    const int bid = s_bid;
    const int idx = bid * 256 + threadIdx.x;

    int v = (idx < n) ? cnt[idx] : 0;
    int incl = block_scan_incl(v);
    if (threadIdx.x == 255) s_total = incl;
    __syncthreads();

    if (threadIdx.x == 0) {
        volatile unsigned long long* st = g_state;
        unsigned long long pkt =
            ((unsigned long long)s_total << 2) | (bid == 0 ? 2ull : 1ull);
        __threadfence();
        st[bid] = pkt;
        int excl = 0;
        if (bid > 0) {
            int j = bid - 1;
            while (true) {
                unsigned long long sv = st[j];
                unsigned f = (unsigned)(sv & 3ull);
                if (f == 0) continue;
                excl += (int)(sv >> 2);
                if (f == 2) break;
                j--;
            }
            unsigned long long pkt2 =
                ((unsigned long long)(excl + s_total) << 2) | 2ull;
            __threadfence();
            st[bid] = pkt2;
        }
        s_excl = excl;
    }
    __syncthreads();

    const int base = s_excl;
    if (idx < n) {
        int r = base + incl - v;
        rowstart[idx] = r;
        cursor[idx]   = r;
        deg[idx] = rsqrtf(deg[idx] + 1.0f);   // dinv fused (+1 = self-loop)
    }
    if (bid == (n + 255) / 256 - 1 && threadIdx.x == 255)
        rowstart[n] = base + s_total;
}

// ---------------- CSR fill: slot <- (src, norm) ------------------------------
__global__ void csr_fill_kernel(const int* __restrict__ src,
                                const int* __restrict__ dst,
                                const float* __restrict__ w,
                                const float* __restrict__ dinv,
                                int* __restrict__ cursor,
                                int2* __restrict__ csr, int e) {
    int i = blockIdx.x * blockDim.x + threadIdx.x;
    if (i >= e) return;
    int s = src[i], d = dst[i];
    float nrm = dinv[s] * w[i] * dinv[d];
    int pos = atomicAdd(&cursor[d], 1);
    csr[pos] = make_int2(s, __float_as_int(nrm));
}

// ---------------- CSR gather over fp16 features, fp32 accumulate -------------
__device__ __forceinline__ float4 h4_to_f4(uint2 u) {
    __half2 a = *(__half2*)&u.x;
    __half2 b = *(__half2*)&u.y;
    float2 fa = __half22float2(a);
    float2 fb = __half22float2(b);
    return make_float4(fa.x, fa.y, fb.x, fb.y);
}

template <int DO_LN>
__global__ __launch_bounds__(256)
void gather_kernel(const int* __restrict__ rowstart,
                   const int2* __restrict__ csr,
                   const float* __restrict__ dinv,
                   const __half* __restrict__ feat,
                   const float* __restrict__ b2,
                   const float* __restrict__ gamma,
                   const float* __restrict__ beta,
                   float* __restrict__ outb, int n) {
    const int node = (blockIdx.x * blockDim.x + threadIdx.x) >> 5;
    const int lane = threadIdx.x & 31;
    if (node >= n) return;

    const uint2* fp = (const uint2*)feat;   // row = 32 uint2
    float dv = dinv[node];
    float4 acc = h4_to_f4(fp[node * 32 + lane]);
    acc.x *= dv * dv; acc.y *= dv * dv; acc.z *= dv * dv; acc.w *= dv * dv;

    const int beg = rowstart[node];
    const int end = rowstart[node + 1];

    int j = beg;
    for (; j + 3 < end; j += 4) {
        int2 e0 = csr[j], e1 = csr[j + 1], e2 = csr[j + 2], e3 = csr[j + 3];
        uint2 r0 = fp[e0.x * 32 + lane];
        uint2 r1 = fp[e1.x * 32 + lane];
        uint2 r2 = fp[e2.x * 32 + lane];
        uint2 r3 = fp[e3.x * 32 + lane];
        float4 v0 = h4_to_f4(r0), v1 = h4_to_f4(r1);
        float4 v2 = h4_to_f4(r2), v3 = h4_to_f4(r3);
        float n0 = __int_as_float(e0.y), n1 = __int_as_float(e1.y);
        float n2 = __int_as_float(e2.y), n3 = __int_as_float(e3.y);
        acc.x = fmaf(v0.x, n0, acc.x); acc.y = fmaf(v0.y, n0, acc.y);
        acc.z = fmaf(v0.z, n0, acc.z); acc.w = fmaf(v0.w, n0, acc.w);
        acc.x = fmaf(v1.x, n1, acc.x); acc.y = fmaf(v1.y, n1, acc.y);
        acc.z = fmaf(v1.z, n1, acc.z); acc.w = fmaf(v1.w, n1, acc.w);
        acc.x = fmaf(v2.x, n2, acc.x); acc.y = fmaf(v2.y, n2, acc.y);
        acc.z = fmaf(v2.z, n2, acc.z); acc.w = fmaf(v2.w, n2, acc.w);
        acc.x = fmaf(v3.x, n3, acc.x); acc.y = fmaf(v3.y, n3, acc.y);
        acc.z = fmaf(v3.z, n3, acc.z); acc.w = fmaf(v3.w, n3, acc.w);
    }
    for (; j < end; j++) {
        int2 e0 = csr[j];
        float4 v0 = h4_to_f4(fp[e0.x * 32 + lane]);
        float n0 = __int_as_float(e0.y);
        acc.x = fmaf(v0.x, n0, acc.x); acc.y = fmaf(v0.y, n0, acc.y);
        acc.z = fmaf(v0.z, n0, acc.z); acc.w = fmaf(v0.w, n0, acc.w);
    }

    if (DO_LN) {
        float4 bb = *(const float4*)(b2 + lane * 4);
        acc.x += bb.x; acc.y += bb.y; acc.z += bb.z; acc.w += bb.w;

        float s = acc.x + acc.y + acc.z + acc.w;
#pragma unroll
        for (int o = 16; o > 0; o >>= 1) s += __shfl_xor_sync(0xFFFFFFFFu, s, o);
        float mu = s * (1.0f / DIN);

        float dx = acc.x - mu, dy = acc.y - mu, dz = acc.z - mu, dw = acc.w - mu;
        float q = dx * dx + dy * dy + dz * dz + dw * dw;
#pragma unroll
        for (int o = 16; o > 0; o >>= 1) q += __shfl_xor_sync(0xFFFFFFFFu, q, o);
        float rstd = rsqrtf(q * (1.0f / DIN) + 1e-5f);

        float4 g  = *(const float4*)(gamma + lane * 4);
        float4 bt = *(const float4*)(beta + lane * 4);
        float4 o4;
        o4.x = dx * rstd * g.x + bt.x;
        o4.y = dy * rstd * g.y + bt.y;
        o4.z = dz * rstd * g.z + bt.z;
        o4.w = dw * rstd * g.w + bt.w;
        *(float4*)(outb + (size_t)node * DIN + lane * 4) = o4;
    } else {
        *(float4*)(outb + (size_t)node * DIN + lane * 4) = acc;
    }
}

// ---------------- TF32 tensor-core GEMM --------------------------------------
__device__ __forceinline__ uint32_t f2tf32(float f) {
    uint32_t u;
    asm("cvt.rna.tf32.f32 %0, %1;" : "=r"(u) : "f"(f));
    return u;
}

__device__ __forceinline__ void mma_tf32(float c[4], const uint32_t a[4],
                                         const uint32_t b[2]) {
    asm volatile(
        "mma.sync.aligned.m16n8k8.row.col.f32.tf32.tf32.f32 "
        "{%0,%1,%2,%3}, {%4,%5,%6,%7}, {%8,%9}, {%0,%1,%2,%3};"
        : "+f"(c[0]), "+f"(c[1]), "+f"(c[2]), "+f"(c[3])
        : "r"(a[0]), "r"(a[1]), "r"(a[2]), "r"(a[3]), "r"(b[0]), "r"(b[1]));
}

#define LDPAD 36

// OUT_HALF=1 -> C is __half (written as half2); else float (float2)
template <int OUT_HALF>
__global__ __launch_bounds__(256)
void gemm_tf32_kernel(const float* __restrict__ A, const float* __restrict__ W,
                      const float* __restrict__ bias, void* __restrict__ Cv,
                      int M, int K, int Nout, int doRelu) {
    __shared__ uint32_t As[128 * LDPAD];
    __shared__ uint32_t Ws[128 * LDPAD];

    const int tid  = threadIdx.x;
    const int lane = tid & 31;
    const int warp = tid >> 5;
    const int wm   = warp & 3;
    const int wn   = warp >> 2;
    const int gid  = lane >> 2;
    const int tig  = lane & 3;
    const int m0   = blockIdx.x * 128;
    const int n0   = blockIdx.y * 128;

    const int lrow = tid >> 3;
    const int lkq  = tid & 7;

    float acc[2][8][4];
#pragma unroll
    for (int i = 0; i < 2; i++)
#pragma unroll
        for (int j = 0; j < 8; j++)
#pragma unroll
            for (int q = 0; q < 4; q++) acc[i][j][q] = 0.f;

    const int nt = K / 32;
    for (int kt = 0; kt < nt; kt++) {
        const int kbase = kt * 32;
        float4 av[4], wv[4];
#pragma unroll
        for (int l = 0; l < 4; l++) {
            int row = lrow + l * 32;
            av[l] = (m0 + row < M)
                  ? *(const float4*)(A + (size_t)(m0 + row) * K + kbase + lkq * 4)
                  : make_float4(0.f, 0.f, 0.f, 0.f);
            wv[l] = *(const float4*)(W + (size_t)(n0 + row) * K + kbase + lkq * 4);
        }
        if (kt > 0) __syncthreads();
#pragma unroll
        for (int l = 0; l < 4; l++) {
            int row = lrow + l * 32;
            uint4 ua = make_uint4(f2tf32(av[l].x), f2tf32(av[l].y),
                                  f2tf32(av[l].z), f2tf32(av[l].w));
            uint4 uw = make_uint4(f2tf32(wv[l].x), f2tf32(wv[l].y),
                                  f2tf32(wv[l].z), f2tf32(wv[l].w));
            *(uint4*)&As[row * LDPAD + lkq * 4] = ua;
            *(uint4*)&Ws[row * LDPAD + lkq * 4] = uw;
        }
        __syncthreads();

#pragma unroll
        for (int ks = 0; ks < 4; ks++) {
            const int k8 = ks * 8;
            uint32_t af[2][4];
#pragma unroll
            for (int mt = 0; mt < 2; mt++) {
                int rbase = wm * 32 + mt * 16;
                af[mt][0] = As[(rbase + gid) * LDPAD + k8 + tig];
                af[mt][1] = As[(rbase + gid + 8) * LDPAD + k8 + tig];
                af[mt][2] = As[(rbase + gid) * LDPAD + k8 + tig + 4];
                af[mt][3] = As[(rbase + gid + 8) * LDPAD + k8 + tig + 4];
            }
            uint32_t bf[8][2];
#pragma unroll
            for (int ntl = 0; ntl < 8; ntl++) {
                int col = wn * 64 + ntl * 8 + gid;
                bf[ntl][0] = Ws[col * LDPAD + k8 + tig];
                bf[ntl][1] = Ws[col * LDPAD + k8 + tig + 4];
            }
#pragma unroll
            for (int mt = 0; mt < 2; mt++)
#pragma unroll
                for (int ntl = 0; ntl < 8; ntl++)
                    mma_tf32(acc[mt][ntl], af[mt], bf[ntl]);
        }
    }

#pragma unroll
    for (int mt = 0; mt < 2; mt++) {
        int row0 = m0 + wm * 32 + mt * 16 + gid;
        int row1 = row0 + 8;
#pragma unroll
        for (int ntl = 0; ntl < 8; ntl++) {
            int col = n0 + wn * 64 + ntl * 8 + tig * 2;
            float bx = 0.f, by = 0.f;
            if (bias) { bx = bias[col]; by = bias[col + 1]; }
            float2 v0 = make_float2(acc[mt][ntl][0] + bx, acc[mt][ntl][1] + by);
            float2 v1 = make_float2(acc[mt][ntl][2] + bx, acc[mt][ntl][3] + by);
            if (doRelu) {
                v0.x = fmaxf(v0.x, 0.f); v0.y = fmaxf(v0.y, 0.f);
                v1.x = fmaxf(v1.x, 0.f); v1.y = fmaxf(v1.y, 0.f);
            }
            if (OUT_HALF) {
                __half2* C = (__half2*)Cv;
                if (row0 < M) C[((size_t)row0 * Nout + col) >> 1] = __floats2half2_rn(v0.x, v0.y);
                if (row1 < M) C[((size_t)row1 * Nout + col) >> 1] = __floats2half2_rn(v1.x, v1.y);
            } else {
                float* C = (float*)Cv;
                if (row0 < M) *(float2*)(C + (size_t)row0 * Nout + col) = v0;
                if (row1 < M) *(float2*)(C + (size_t)row1 * Nout + col) = v1;
            }
        }
    }
}

// -----------------------------------------------------------------------------
extern "C" void kernel_launch(void* const* d_in, const int* in_sizes, int n_in,
                              void* d_out, int out_size) {
    const float* x     = (const float*)d_in[0];
    const void*  ei    = d_in[1];
    const float* ew    = (const float*)d_in[2];
    const float* W1    = (const float*)d_in[3];
    const float* b1    = (const float*)d_in[4];
    const float* W2    = (const float*)d_in[5];
    const float* b2    = (const float*)d_in[6];
    const float* gamma = (const float*)d_in[7];
    const float* beta  = (const float*)d_in[8];
    float*       out   = (float*)d_out;

    float *dinv, *agg1, *h;
    __half *xh, *ph;
    int *src, *dst, *cnt, *rowstart, *cursor;
    int2 *csr;
    cudaGetSymbolAddress((void**)&dinv,     g_dinv);
    cudaGetSymbolAddress((void**)&agg1,     g_agg1);
    cudaGetSymbolAddress((void**)&h,        g_h);
    cudaGetSymbolAddress((void**)&xh,       g_xh);
    cudaGetSymbolAddress((void**)&ph,       g_ph);
    cudaGetSymbolAddress((void**)&src,      g_src);
    cudaGetSymbolAddress((void**)&dst,      g_dst);
    cudaGetSymbolAddress((void**)&cnt,      g_count);
    cudaGetSymbolAddress((void**)&rowstart, g_rowstart);
    cudaGetSymbolAddress((void**)&cursor,   g_cursor);
    cudaGetSymbolAddress((void**)&csr,      g_csr);

    const int n = NN, e = EE;

    // 1. prep: zero scratch, detect dtype, x->fp16   (1 launch)
    prep_kernel<<<1024, 256>>>((const int*)ei, x, xh, dinv, cnt);

    // 2. convert + weighted degree + counts
    convert_deg_kernel<<<(e + 255) / 256, 256>>>(ei, ew, src, dst, dinv, cnt, e);

    // 3. single-pass scan (+dinv, cursor init)
    scan_lookback_kernel<<<NBLK, 256>>>(cnt, dinv, rowstart, cursor, n);

    // 4. CSR fill
    csr_fill_kernel<<<(e + 255) / 256, 256>>>(src, dst, ew, dinv, cursor, csr, e);

    // 5. agg1 = A_norm @ x   (fp16 gather, fp32 accumulate)
    gather_kernel<0><<<(n * 32 + 255) / 256, 256>>>(rowstart, csr, dinv, xh,
                                                    nullptr, nullptr, nullptr,
                                                    agg1, n);

    // 6. h = relu(agg1 @ W1^T + b1)
    {
        dim3 grid((n + 127) / 128, DH / 128);
        gemm_tf32_kernel<0><<<grid, 256>>>(agg1, W1, b1, h, n, DIN, DH, 1);
    }

    // 7. p = h @ W2^T -> fp16 (bias deferred to fused LN)
    {
        dim3 grid((n + 127) / 128, DIN / 128);
        gemm_tf32_kernel<1><<<grid, 256>>>(h, W2, nullptr, ph, n, DH, DIN, 0);
    }

    // 8. out = LN(A_norm @ p + b2) * gamma + beta   (fp16 gather + LN fused)
    gather_kernel<1><<<(n * 32 + 255) / 256, 256>>>(rowstart, csr, dinv, ph,
                                                    b2, gamma, beta, out, n);
}

// round 9
// speedup vs baseline: 2.6589x; 1.3433x over previous
#include <cuda_runtime.h>
#include <cuda_fp16.h>
#include <cstdint>
#include <cstddef>

#define NN   50000
#define EE   800000
#define DIN  128
#define DH   256
#define NBLK ((NN + 255) / 256)   // 196 scan blocks

// ---------------- scratch (device globals; no allocation allowed) ------------
__device__ float  g_dinv[NN];             // weighted in-degree -> rsqrt in place
__device__ int    g_count[NN];            // per-dst edge count
__device__ int    g_rowstart[NN + 1];     // CSR offsets
__device__ int    g_cursor[NN];           // fill cursors
__device__ int2   g_csr[EE];              // packed (src, nrm-as-bits)
__device__ __half g_xh[NN * DIN];         // x in fp16
__device__ __half g_a1h[NN * DIN];        // A @ x in fp16 (GEMM1 input)
__device__ __half g_hh[(size_t)NN * DH];  // relu(agg1 @ W1^T + b1) fp16
__device__ __half g_ph[NN * DIN];         // h @ W2^T in fp16
__device__ __half g_w1h[DH * DIN];        // W1 fp16
__device__ __half g_w2h[DIN * DH];        // W2 fp16
__device__ int    g_src[EE];
__device__ int    g_dst[EE];
__device__ int    g_is64;
__device__ int    g_ticket;                        // lookback ticket
__device__ unsigned long long g_state[NBLK];       // value<<2 | flag

// ---------------- prep: zero scratch + dtype detect + fp16 conversions -------
__global__ void prep_kernel(const int* __restrict__ raw,
                            const float* __restrict__ x,
                            const float* __restrict__ W1,
                            const float* __restrict__ W2,
                            float* __restrict__ deg,
                            int* __restrict__ cnt) {
    const int gtid   = blockIdx.x * blockDim.x + threadIdx.x;
    const int stride = gridDim.x * blockDim.x;

    for (int i = gtid; i < NN; i += stride) { deg[i] = 0.f; cnt[i] = 0; }
    for (int i = gtid; i < NBLK; i += stride) g_state[i] = 0ull;
    if (gtid == 0) g_ticket = 0;

    // x -> fp16
    const int pairs = NN * DIN / 2;
    const float2* xin = (const float2*)x;
    __half2* xo = (__half2*)g_xh;
    for (int i = gtid; i < pairs; i += stride) {
        float2 v = xin[i];
        xo[i] = __floats2half2_rn(v.x, v.y);
    }
    // W1, W2 -> fp16
    const int wp = DH * DIN / 2;
    const float2* w1in = (const float2*)W1;
    const float2* w2in = (const float2*)W2;
    __half2* w1o = (__half2*)g_w1h;
    __half2* w2o = (__half2*)g_w2h;
    for (int i = gtid; i < wp; i += stride) {
        float2 a = w1in[i];
        float2 b = w2in[i];
        w1o[i] = __floats2half2_rn(a.x, a.y);
        w2o[i] = __floats2half2_rn(b.x, b.y);
    }

    // dtype detect (block 0): int64 little-endian -> odd words all zero
    if (blockIdx.x == 0) {
        int odd = (threadIdx.x < 128) ? raw[2 * threadIdx.x + 1] : 0;
        int any = __syncthreads_or(odd != 0);
        if (threadIdx.x == 0) g_is64 = any ? 0 : 1;
    }
}

// ------- convert indices + weighted in-degree + per-dst edge counts ----------
__global__ void convert_deg_kernel(const void* __restrict__ raw,
                                   const float* __restrict__ w,
                                   int* __restrict__ src,
                                   int* __restrict__ dst,
                                   float* __restrict__ deg,
                                   int* __restrict__ cnt, int e) {
    int i = blockIdx.x * blockDim.x + threadIdx.x;
    if (i >= e) return;
    int s, d;
    if (g_is64) {
        const long long* p = (const long long*)raw;
        s = (int)p[i];
        d = (int)p[(size_t)e + i];
    } else {
        const int* p = (const int*)raw;
        s = p[i];
        d = p[e + i];
    }
    src[i] = s;
    dst[i] = d;
    atomicAdd(&deg[d], w[i]);
    atomicAdd(&cnt[d], 1);
}

// ---------------- single-pass lookback scan (+dinv fused) --------------------
__device__ __forceinline__ int block_scan_incl(int v) {
    const int lane = threadIdx.x & 31;
    const int warp = threadIdx.x >> 5;
    int s = v;
#pragma unroll
    for (int o = 1; o < 32; o <<= 1) {
        int t = __shfl_up_sync(0xFFFFFFFFu, s, o);
        if (lane >= o) s += t;
    }
    __shared__ int wsum[8];
    if (lane == 31) wsum[warp] = s;
    __syncthreads();
    if (warp == 0 && lane < 8) {
        int ws = wsum[lane];
#pragma unroll
        for (int o = 1; o < 8; o <<= 1) {
            int t = __shfl_up_sync(0xFFu, ws, o);
            if (lane >= o) ws += t;
        }
        wsum[lane] = ws;
    }
    __syncthreads();
    return s + (warp > 0 ? wsum[warp - 1] : 0);
}

__global__ void scan_lookback_kernel(const int* __restrict__ cnt,
                                     float* __restrict__ deg,   // -> dinv
                                     int* __restrict__ rowstart,
                                     int* __restrict__ cursor, int n) {
    __shared__ int s_bid, s_total, s_excl;
    if (threadIdx.x == 0) s_bid = atomicAdd(&g_ticket, 1);
    __syncthreads();
    const int bid = s_bid;
    const int idx = bid * 256 + threadIdx.x;

    int v = (idx < n) ? cnt[idx] : 0;
    int incl = block_scan_incl(v);
    if (threadIdx.x == 255) s_total = incl;
    __syncthreads();

    if (threadIdx.x == 0) {
        volatile unsigned long long* st = g_state;
        unsigned long long pkt =
            ((unsigned long long)s_total << 2) | (bid == 0 ? 2ull : 1ull);
        __threadfence();
        st[bid] = pkt;
        int excl = 0;
        if (bid > 0) {
            int j = bid - 1;
            while (true) {
                unsigned long long sv = st[j];
                unsigned f = (unsigned)(sv & 3ull);
                if (f == 0) continue;
                excl += (int)(sv >> 2);
                if (f == 2) break;
                j--;
            }
            unsigned long long pkt2 =
                ((unsigned long long)(excl + s_total) << 2) | 2ull;
            __threadfence();
            st[bid] = pkt2;
        }
        s_excl = excl;
    }
    __syncthreads();

    const int base = s_excl;
    if (idx < n) {
        int r = base + incl - v;
        rowstart[idx] = r;
        cursor[idx]   = r;
        deg[idx] = rsqrtf(deg[idx] + 1.0f);   // dinv fused (+1 = self-loop)
    }
    if (bid == (n + 255) / 256 - 1 && threadIdx.x == 255)
        rowstart[n] = base + s_total;
}

// ---------------- CSR fill: slot <- (src, norm) ------------------------------
__global__ void csr_fill_kernel(const int* __restrict__ src,
                                const int* __restrict__ dst,
                                const float* __restrict__ w,
                                const float* __restrict__ dinv,
                                int* __restrict__ cursor,
                                int2* __restrict__ csr, int e) {
    int i = blockIdx.x * blockDim.x + threadIdx.x;
    if (i >= e) return;
    int s = src[i], d = dst[i];
    float nrm = dinv[s] * w[i] * dinv[d];
    int pos = atomicAdd(&cursor[d], 1);
    csr[pos] = make_int2(s, __float_as_int(nrm));
}

// ---------------- CSR gather over fp16 features, fp32 accumulate -------------
__device__ __forceinline__ float4 h4_to_f4(uint2 u) {
    __half2 a = *(__half2*)&u.x;
    __half2 b = *(__half2*)&u.y;
    float2 fa = __half22float2(a);
    float2 fb = __half22float2(b);
    return make_float4(fa.x, fa.y, fb.x, fb.y);
}

// DO_LN=0: write fp16 (outb = __half*). DO_LN=1: LN, write fp32 (outb = float*)
template <int DO_LN>
__global__ __launch_bounds__(256)
void gather_kernel(const int* __restrict__ rowstart,
                   const int2* __restrict__ csr,
                   const float* __restrict__ dinv,
                   const __half* __restrict__ feat,
                   const float* __restrict__ b2,
                   const float* __restrict__ gamma,
                   const float* __restrict__ beta,
                   void* __restrict__ outb, int n) {
    const int node = (blockIdx.x * blockDim.x + threadIdx.x) >> 5;
    const int lane = threadIdx.x & 31;
    if (node >= n) return;

    const uint2* fp = (const uint2*)feat;   // row = 32 uint2
    float dv = dinv[node];
    float4 acc = h4_to_f4(fp[node * 32 + lane]);
    acc.x *= dv * dv; acc.y *= dv * dv; acc.z *= dv * dv; acc.w *= dv * dv;

    const int beg = rowstart[node];
    const int end = rowstart[node + 1];

    int j = beg;
    for (; j + 3 < end; j += 4) {
        int2 e0 = csr[j], e1 = csr[j + 1], e2 = csr[j + 2], e3 = csr[j + 3];
        uint2 r0 = fp[e0.x * 32 + lane];
        uint2 r1 = fp[e1.x * 32 + lane];
        uint2 r2 = fp[e2.x * 32 + lane];
        uint2 r3 = fp[e3.x * 32 + lane];
        float4 v0 = h4_to_f4(r0), v1 = h4_to_f4(r1);
        float4 v2 = h4_to_f4(r2), v3 = h4_to_f4(r3);
        float n0 = __int_as_float(e0.y), n1 = __int_as_float(e1.y);
        float n2 = __int_as_float(e2.y), n3 = __int_as_float(e3.y);
        acc.x = fmaf(v0.x, n0, acc.x); acc.y = fmaf(v0.y, n0, acc.y);
        acc.z = fmaf(v0.z, n0, acc.z); acc.w = fmaf(v0.w, n0, acc.w);
        acc.x = fmaf(v1.x, n1, acc.x); acc.y = fmaf(v1.y, n1, acc.y);
        acc.z = fmaf(v1.z, n1, acc.z); acc.w = fmaf(v1.w, n1, acc.w);
        acc.x = fmaf(v2.x, n2, acc.x); acc.y = fmaf(v2.y, n2, acc.y);
        acc.z = fmaf(v2.z, n2, acc.z); acc.w = fmaf(v2.w, n2, acc.w);
        acc.x = fmaf(v3.x, n3, acc.x); acc.y = fmaf(v3.y, n3, acc.y);
        acc.z = fmaf(v3.z, n3, acc.z); acc.w = fmaf(v3.w, n3, acc.w);
    }
    for (; j < end; j++) {
        int2 e0 = csr[j];
        float4 v0 = h4_to_f4(fp[e0.x * 32 + lane]);
        float n0 = __int_as_float(e0.y);
        acc.x = fmaf(v0.x, n0, acc.x); acc.y = fmaf(v0.y, n0, acc.y);
        acc.z = fmaf(v0.z, n0, acc.z); acc.w = fmaf(v0.w, n0, acc.w);
    }

    if (DO_LN) {
        float4 bb = *(const float4*)(b2 + lane * 4);
        acc.x += bb.x; acc.y += bb.y; acc.z += bb.z; acc.w += bb.w;

        float s = acc.x + acc.y + acc.z + acc.w;
#pragma unroll
        for (int o = 16; o > 0; o >>= 1) s += __shfl_xor_sync(0xFFFFFFFFu, s, o);
        float mu = s * (1.0f / DIN);

        float dx = acc.x - mu, dy = acc.y - mu, dz = acc.z - mu, dw = acc.w - mu;
        float q = dx * dx + dy * dy + dz * dz + dw * dw;
#pragma unroll
        for (int o = 16; o > 0; o >>= 1) q += __shfl_xor_sync(0xFFFFFFFFu, q, o);
        float rstd = rsqrtf(q * (1.0f / DIN) + 1e-5f);

        float4 g  = *(const float4*)(gamma + lane * 4);
        float4 bt = *(const float4*)(beta + lane * 4);
        float4 o4;
        o4.x = dx * rstd * g.x + bt.x;
        o4.y = dy * rstd * g.y + bt.y;
        o4.z = dz * rstd * g.z + bt.z;
        o4.w = dw * rstd * g.w + bt.w;
        *(float4*)((float*)outb + (size_t)node * DIN + lane * 4) = o4;
    } else {
        __half2 h0 = __floats2half2_rn(acc.x, acc.y);
        __half2 h1 = __floats2half2_rn(acc.z, acc.w);
        uint2 pk = make_uint2(*(uint32_t*)&h0, *(uint32_t*)&h1);
        ((uint2*)outb)[node * 32 + lane] = pk;
    }
}

// ---------------- FP16 tensor-core GEMM (m16n8k16, fp32 accum) ---------------
// C[m][n] = sum_k A[m][k] * W[n][k]; A:[M,K] half row-major, W:[Nout,K] half.
// Block 128x128, 256 thr (8 warps 4x2), warp 32x64 = 2x8 m16n8, BK=32.
__device__ __forceinline__ void mma_f16(float c[4], const uint32_t a[4],
                                        const uint32_t b[2]) {
    asm volatile(
        "mma.sync.aligned.m16n8k16.row.col.f32.f16.f16.f32 "
        "{%0,%1,%2,%3}, {%4,%5,%6,%7}, {%8,%9}, {%0,%1,%2,%3};"
        : "+f"(c[0]), "+f"(c[1]), "+f"(c[2]), "+f"(c[3])
        : "r"(a[0]), "r"(a[1]), "r"(a[2]), "r"(a[3]), "r"(b[0]), "r"(b[1]));
}

#define HST 20   // smem row stride in uints (16 data + 4 pad, 16B-aligned rows)

__global__ __launch_bounds__(256)
void gemm_f16_kernel(const __half* __restrict__ A, const __half* __restrict__ W,
                     const float* __restrict__ bias, __half* __restrict__ C,
                     int M, int K, int Nout, int doRelu) {
    __shared__ uint32_t As[128 * HST];
    __shared__ uint32_t Ws[128 * HST];

    const int tid  = threadIdx.x;
    const int lane = tid & 31;
    const int warp = tid >> 5;
    const int wm   = warp & 3;        // m offset wm*32
    const int wn   = warp >> 2;       // n offset wn*64
    const int gid  = lane >> 2;       // 0..7
    const int tig  = lane & 3;        // 0..3
    const int m0   = blockIdx.x * 128;
    const int n0   = blockIdx.y * 128;

    // loaders: tile = 128 rows x 4 uint4 (32 halfs); 512 uint4; 2 per thread
    const int lr0 = tid >> 1, lq0 = (tid & 1) * 2;   // rows 0..127, q 0 or 2
    // thread covers q and q+1 (two uint4 = 8 uints = 32 halfs? no: 2 uint4 = row half)
    // simpler: idx0 = tid, idx1 = tid + 256; row = idx>>2, q = idx&3

    float acc[2][8][4];
#pragma unroll
    for (int i = 0; i < 2; i++)
#pragma unroll
        for (int j = 0; j < 8; j++)
#pragma unroll
            for (int q = 0; q < 4; q++) acc[i][j][q] = 0.f;

    const int nt = K / 32;
    for (int kt = 0; kt < nt; kt++) {
        const int kb = kt * 32;   // half offset
        uint4 la[2], lw[2];
#pragma unroll
        for (int l = 0; l < 2; l++) {
            int idx = tid + l * 256;
            int row = idx >> 2, q = idx & 3;
            la[l] = (m0 + row < M)
                  ? *(const uint4*)(A + (size_t)(m0 + row) * K + kb + q * 8)
                  : make_uint4(0u, 0u, 0u, 0u);
            lw[l] = *(const uint4*)(W + (size_t)(n0 + row) * K + kb + q * 8);
        }
        if (kt > 0) __syncthreads();
#pragma unroll
        for (int l = 0; l < 2; l++) {
            int idx = tid + l * 256;
            int row = idx >> 2, q = idx & 3;
            *(uint4*)&As[row * HST + q * 4] = la[l];
            *(uint4*)&Ws[row * HST + q * 4] = lw[l];
        }
        __syncthreads();

#pragma unroll
        for (int ks = 0; ks < 2; ks++) {
            const int k2 = ks * 8;   // uint offset within row
            uint32_t af[2][4];
#pragma unroll
            for (int mt = 0; mt < 2; mt++) {
                int rb = wm * 32 + mt * 16;
                af[mt][0] = As[(rb + gid) * HST + k2 + tig];
                af[mt][1] = As[(rb + gid + 8) * HST + k2 + tig];
                af[mt][2] = As[(rb + gid) * HST + k2 + tig + 4];
                af[mt][3] = As[(rb + gid + 8) * HST + k2 + tig + 4];
            }
            uint32_t bf[8][2];
#pragma unroll
            for (int ntl = 0; ntl < 8; ntl++) {
                int col = wn * 64 + ntl * 8 + gid;
                bf[ntl][0] = Ws[col * HST + k2 + tig];
                bf[ntl][1] = Ws[col * HST + k2 + tig + 4];
            }
#pragma unroll
            for (int mt = 0; mt < 2; mt++)
#pragma unroll
                for (int ntl = 0; ntl < 8; ntl++)
                    mma_f16(acc[mt][ntl], af[mt], bf[ntl]);
        }
    }

    // epilogue: fp32 + bias (+relu) -> half2
#pragma unroll
    for (int mt = 0; mt < 2; mt++) {
        int row0 = m0 + wm * 32 + mt * 16 + gid;
        int row1 = row0 + 8;
#pragma unroll
        for (int ntl = 0; ntl < 8; ntl++) {
            int col = n0 + wn * 64 + ntl * 8 + tig * 2;
            float bx = 0.f, by = 0.f;
            if (bias) { bx = bias[col]; by = bias[col + 1]; }
            float2 v0 = make_float2(acc[mt][ntl][0] + bx, acc[mt][ntl][1] + by);
            float2 v1 = make_float2(acc[mt][ntl][2] + bx, acc[mt][ntl][3] + by);
            if (doRelu) {
                v0.x = fmaxf(v0.x, 0.f); v0.y = fmaxf(v0.y, 0.f);
                v1.x = fmaxf(v1.x, 0.f); v1.y = fmaxf(v1.y, 0.f);
            }
            if (row0 < M)
                *(__half2*)(C + (size_t)row0 * Nout + col) = __floats2half2_rn(v0.x, v0.y);
            if (row1 < M)
                *(__half2*)(C + (size_t)row1 * Nout + col) = __floats2half2_rn(v1.x, v1.y);
        }
    }
}

// -----------------------------------------------------------------------------
extern "C" void kernel_launch(void* const* d_in, const int* in_sizes, int n_in,
                              void* d_out, int out_size) {
    const float* x     = (const float*)d_in[0];
    const void*  ei    = d_in[1];
    const float* ew    = (const float*)d_in[2];
    const float* W1    = (const float*)d_in[3];
    const float* b1    = (const float*)d_in[4];
    const float* W2    = (const float*)d_in[5];
    const float* b2    = (const float*)d_in[6];
    const float* gamma = (const float*)d_in[7];
    const float* beta  = (const float*)d_in[8];
    float*       out   = (float*)d_out;

    float *dinv;
    __half *xh, *a1h, *hh, *ph, *w1h, *w2h;
    int *src, *dst, *cnt, *rowstart, *cursor;
    int2 *csr;
    cudaGetSymbolAddress((void**)&dinv,     g_dinv);
    cudaGetSymbolAddress((void**)&xh,       g_xh);
    cudaGetSymbolAddress((void**)&a1h,      g_a1h);
    cudaGetSymbolAddress((void**)&hh,       g_hh);
    cudaGetSymbolAddress((void**)&ph,       g_ph);
    cudaGetSymbolAddress((void**)&w1h,      g_w1h);
    cudaGetSymbolAddress((void**)&w2h,      g_w2h);
    cudaGetSymbolAddress((void**)&src,      g_src);
    cudaGetSymbolAddress((void**)&dst,      g_dst);
    cudaGetSymbolAddress((void**)&cnt,      g_count);
    cudaGetSymbolAddress((void**)&rowstart, g_rowstart);
    cudaGetSymbolAddress((void**)&cursor,   g_cursor);
    cudaGetSymbolAddress((void**)&csr,      g_csr);

    const int n = NN, e = EE;

    // 1. prep: zero scratch, detect dtype, x/W1/W2 -> fp16
    prep_kernel<<<1024, 256>>>((const int*)ei, x, W1, W2, dinv, cnt);

    // 2. convert + weighted degree + counts
    convert_deg_kernel<<<(e + 255) / 256, 256>>>(ei, ew, src, dst, dinv, cnt, e);

    // 3. single-pass scan (+dinv, cursor init)
    scan_lookback_kernel<<<NBLK, 256>>>(cnt, dinv, rowstart, cursor, n);

    // 4. CSR fill
    csr_fill_kernel<<<(e + 255) / 256, 256>>>(src, dst, ew, dinv, cursor, csr, e);

    // 5. agg1 = A_norm @ x  (fp16 gather -> fp16)
    gather_kernel<0><<<(n * 32 + 255) / 256, 256>>>(rowstart, csr, dinv, xh,
                                                    nullptr, nullptr, nullptr,
                                                    a1h, n);

    // 6. h = relu(agg1 @ W1^T + b1)  [fp16 MMA]
    {
        dim3 grid((n + 127) / 128, DH / 128);
        gemm_f16_kernel<<<grid, 256>>>(a1h, w1h, b1, hh, n, DIN, DH, 1);
    }

    // 7. p = h @ W2^T  [fp16 MMA, bias deferred]
    {
        dim3 grid((n + 127) / 128, DIN / 128);
        gemm_f16_kernel<<<grid, 256>>>(hh, w2h, nullptr, ph, n, DH, DIN, 0);
    }

    // 8. out = LN(A_norm @ p + b2) * gamma + beta
    gather_kernel<1><<<(n * 32 + 255) / 256, 256>>>(rowstart, csr, dinv, ph,
                                                    b2, gamma, beta, out, n);
}

// round 10
// speedup vs baseline: 3.0366x; 1.1420x over previous
#include <cuda_runtime.h>
#include <cuda_fp16.h>
#include <cstdint>
#include <cstddef>

#define NN   50000
#define EE   800000
#define DIN  128
#define DH   256
#define NBLK ((NN + 255) / 256)   // 196 scan blocks

// ---------------- scratch (device globals; no allocation allowed) ------------
__device__ float  g_dinv[NN];             // weighted in-degree -> rsqrt in place
__device__ int    g_count[NN];            // per-dst edge count
__device__ int    g_rowstart[NN + 1];     // CSR offsets
__device__ int    g_cursor[NN];           // fill cursors
__device__ int2   g_csr[EE];              // packed (src, nrm-as-bits)
__device__ __half g_xh[NN * DIN];         // x in fp16
__device__ __half g_a1h[NN * DIN];        // A @ x in fp16 (GEMM input)
__device__ __half g_ph[NN * DIN];         // fused-GEMM output in fp16
__device__ __half g_w1h[DH * DIN];        // W1 fp16
__device__ __half g_w2h[DIN * DH];        // W2 fp16
__device__ int    g_is64;
__device__ int    g_ticket;                        // lookback ticket
__device__ unsigned long long g_state[NBLK];       // value<<2 | flag

// ---------------- prep: zero scratch + dtype detect + fp16 conversions -------
__global__ void prep_kernel(const int* __restrict__ raw,
                            const float* __restrict__ x,
                            const float* __restrict__ W1,
                            const float* __restrict__ W2,
                            float* __restrict__ deg,
                            int* __restrict__ cnt) {
    const int gtid   = blockIdx.x * blockDim.x + threadIdx.x;
    const int stride = gridDim.x * blockDim.x;

    for (int i = gtid; i < NN; i += stride) { deg[i] = 0.f; cnt[i] = 0; }
    for (int i = gtid; i < NBLK; i += stride) g_state[i] = 0ull;
    if (gtid == 0) g_ticket = 0;

    const int pairs = NN * DIN / 2;
    const float2* xin = (const float2*)x;
    __half2* xo = (__half2*)g_xh;
    for (int i = gtid; i < pairs; i += stride) {
        float2 v = xin[i];
        xo[i] = __floats2half2_rn(v.x, v.y);
    }
    const int wp = DH * DIN / 2;
    const float2* w1in = (const float2*)W1;
    const float2* w2in = (const float2*)W2;
    __half2* w1o = (__half2*)g_w1h;
    __half2* w2o = (__half2*)g_w2h;
    for (int i = gtid; i < wp; i += stride) {
        float2 a = w1in[i];
        float2 b = w2in[i];
        w1o[i] = __floats2half2_rn(a.x, a.y);
        w2o[i] = __floats2half2_rn(b.x, b.y);
    }

    if (blockIdx.x == 0) {
        int odd = (threadIdx.x < 128) ? raw[2 * threadIdx.x + 1] : 0;
        int any = __syncthreads_or(odd != 0);
        if (threadIdx.x == 0) g_is64 = any ? 0 : 1;
    }
}

// ---------------- index decode helper ----------------------------------------
__device__ __forceinline__ void decode_edge(const void* raw, int e, int i,
                                            int& s, int& d) {
    if (g_is64) {
        const long long* p = (const long long*)raw;
        s = (int)p[i];
        d = (int)p[(size_t)e + i];
    } else {
        const int* p = (const int*)raw;
        s = p[i];
        d = p[e + i];
    }
}

// ------- weighted in-degree + per-dst edge counts (no index staging) ---------
__global__ void convert_deg_kernel(const void* __restrict__ raw,
                                   const float* __restrict__ w,
                                   float* __restrict__ deg,
                                   int* __restrict__ cnt, int e) {
    int i = blockIdx.x * blockDim.x + threadIdx.x;
    if (i >= e) return;
    int s, d;
    decode_edge(raw, e, i, s, d);
    atomicAdd(&deg[d], w[i]);
    atomicAdd(&cnt[d], 1);
}

// ---------------- single-pass lookback scan (+dinv fused) --------------------
__device__ __forceinline__ int block_scan_incl(int v) {
    const int lane = threadIdx.x & 31;
    const int warp = threadIdx.x >> 5;
    int s = v;
#pragma unroll
    for (int o = 1; o < 32; o <<= 1) {
        int t = __shfl_up_sync(0xFFFFFFFFu, s, o);
        if (lane >= o) s += t;
    }
    __shared__ int wsum[8];
    if (lane == 31) wsum[warp] = s;
    __syncthreads();
    if (warp == 0 && lane < 8) {
        int ws = wsum[lane];
#pragma unroll
        for (int o = 1; o < 8; o <<= 1) {
            int t = __shfl_up_sync(0xFFu, ws, o);
            if (lane >= o) ws += t;
        }
        wsum[lane] = ws;
    }
    __syncthreads();
    return s + (warp > 0 ? wsum[warp - 1] : 0);
}

__global__ void scan_lookback_kernel(const int* __restrict__ cnt,
                                     float* __restrict__ deg,   // -> dinv
                                     int* __restrict__ rowstart,
                                     int* __restrict__ cursor, int n) {
    __shared__ int s_bid, s_total, s_excl;
    if (threadIdx.x == 0) s_bid = atomicAdd(&g_ticket, 1);
    __syncthreads();
    const int bid = s_bid;
    const int idx = bid * 256 + threadIdx.x;

    int v = (idx < n) ? cnt[idx] : 0;
    int incl = block_scan_incl(v);
    if (threadIdx.x == 255) s_total = incl;
    __syncthreads();

    if (threadIdx.x == 0) {
        volatile unsigned long long* st = g_state;
        unsigned long long pkt =
            ((unsigned long long)s_total << 2) | (bid == 0 ? 2ull : 1ull);
        __threadfence();
        st[bid] = pkt;
        int excl = 0;
        if (bid > 0) {
            int j = bid - 1;
            while (true) {
                unsigned long long sv = st[j];
                unsigned f = (unsigned)(sv & 3ull);
                if (f == 0) continue;
                excl += (int)(sv >> 2);
                if (f == 2) break;
                j--;
            }
            unsigned long long pkt2 =
                ((unsigned long long)(excl + s_total) << 2) | 2ull;
            __threadfence();
            st[bid] = pkt2;
        }
        s_excl = excl;
    }
    __syncthreads();

    const int base = s_excl;
    if (idx < n) {
        int r = base + incl - v;
        rowstart[idx] = r;
        cursor[idx]   = r;
        deg[idx] = rsqrtf(deg[idx] + 1.0f);   // dinv fused (+1 = self-loop)
    }
    if (bid == (n + 255) / 256 - 1 && threadIdx.x == 255)
        rowstart[n] = base + s_total;
}

// ---------------- CSR fill: slot <- (src, norm), raw re-decode ---------------
__global__ void csr_fill_kernel(const void* __restrict__ raw,
                                const float* __restrict__ w,
                                const float* __restrict__ dinv,
                                int* __restrict__ cursor,
                                int2* __restrict__ csr, int e) {
    int i = blockIdx.x * blockDim.x + threadIdx.x;
    if (i >= e) return;
    int s, d;
    decode_edge(raw, e, i, s, d);
    float nrm = dinv[s] * w[i] * dinv[d];
    int pos = atomicAdd(&cursor[d], 1);
    csr[pos] = make_int2(s, __float_as_int(nrm));
}

// ---------------- CSR gather over fp16 features, fp32 accumulate -------------
__device__ __forceinline__ float4 h4_to_f4(uint2 u) {
    __half2 a = *(__half2*)&u.x;
    __half2 b = *(__half2*)&u.y;
    float2 fa = __half22float2(a);
    float2 fb = __half22float2(b);
    return make_float4(fa.x, fa.y, fb.x, fb.y);
}

// DO_LN=0: write fp16 (outb = __half*). DO_LN=1: LN, write fp32 (outb = float*)
template <int DO_LN>
__global__ __launch_bounds__(256)
void gather_kernel(const int* __restrict__ rowstart,
                   const int2* __restrict__ csr,
                   const float* __restrict__ dinv,
                   const __half* __restrict__ feat,
                   const float* __restrict__ b2,
                   const float* __restrict__ gamma,
                   const float* __restrict__ beta,
                   void* __restrict__ outb, int n) {
    const int node = (blockIdx.x * blockDim.x + threadIdx.x) >> 5;
    const int lane = threadIdx.x & 31;
    if (node >= n) return;

    const uint2* fp = (const uint2*)feat;   // row = 32 uint2
    float dv = dinv[node];
    float4 acc = h4_to_f4(fp[node * 32 + lane]);
    acc.x *= dv * dv; acc.y *= dv * dv; acc.z *= dv * dv; acc.w *= dv * dv;

    const int beg = rowstart[node];
    const int end = rowstart[node + 1];

    int j = beg;
    for (; j + 3 < end; j += 4) {
        int2 e0 = csr[j], e1 = csr[j + 1], e2 = csr[j + 2], e3 = csr[j + 3];
        uint2 r0 = fp[e0.x * 32 + lane];
        uint2 r1 = fp[e1.x * 32 + lane];
        uint2 r2 = fp[e2.x * 32 + lane];
        uint2 r3 = fp[e3.x * 32 + lane];
        float4 v0 = h4_to_f4(r0), v1 = h4_to_f4(r1);
        float4 v2 = h4_to_f4(r2), v3 = h4_to_f4(r3);
        float n0 = __int_as_float(e0.y), n1 = __int_as_float(e1.y);
        float n2 = __int_as_float(e2.y), n3 = __int_as_float(e3.y);
        acc.x = fmaf(v0.x, n0, acc.x); acc.y = fmaf(v0.y, n0, acc.y);
        acc.z = fmaf(v0.z, n0, acc.z); acc.w = fmaf(v0.w, n0, acc.w);
        acc.x = fmaf(v1.x, n1, acc.x); acc.y = fmaf(v1.y, n1, acc.y);
        acc.z = fmaf(v1.z, n1, acc.z); acc.w = fmaf(v1.w, n1, acc.w);
        acc.x = fmaf(v2.x, n2, acc.x); acc.y = fmaf(v2.y, n2, acc.y);
        acc.z = fmaf(v2.z, n2, acc.z); acc.w = fmaf(v2.w, n2, acc.w);
        acc.x = fmaf(v3.x, n3, acc.x); acc.y = fmaf(v3.y, n3, acc.y);
        acc.z = fmaf(v3.z, n3, acc.z); acc.w = fmaf(v3.w, n3, acc.w);
    }
    for (; j < end; j++) {
        int2 e0 = csr[j];
        float4 v0 = h4_to_f4(fp[e0.x * 32 + lane]);
        float n0 = __int_as_float(e0.y);
        acc.x = fmaf(v0.x, n0, acc.x); acc.y = fmaf(v0.y, n0, acc.y);
        acc.z = fmaf(v0.z, n0, acc.z); acc.w = fmaf(v0.w, n0, acc.w);
    }

    if (DO_LN) {
        float4 bb = *(const float4*)(b2 + lane * 4);
        acc.x += bb.x; acc.y += bb.y; acc.z += bb.z; acc.w += bb.w;

        float s = acc.x + acc.y + acc.z + acc.w;
#pragma unroll
        for (int o = 16; o > 0; o >>= 1) s += __shfl_xor_sync(0xFFFFFFFFu, s, o);
        float mu = s * (1.0f / DIN);

        float dx = acc.x - mu, dy = acc.y - mu, dz = acc.z - mu, dw = acc.w - mu;
        float q = dx * dx + dy * dy + dz * dz + dw * dw;
#pragma unroll
        for (int o = 16; o > 0; o >>= 1) q += __shfl_xor_sync(0xFFFFFFFFu, q, o);
        float rstd = rsqrtf(q * (1.0f / DIN) + 1e-5f);

        float4 g  = *(const float4*)(gamma + lane * 4);
        float4 bt = *(const float4*)(beta + lane * 4);
        float4 o4;
        o4.x = dx * rstd * g.x + bt.x;
        o4.y = dy * rstd * g.y + bt.y;
        o4.z = dz * rstd * g.z + bt.z;
        o4.w = dw * rstd * g.w + bt.w;
        *(float4*)((float*)outb + (size_t)node * DIN + lane * 4) = o4;
    } else {
        __half2 h0 = __floats2half2_rn(acc.x, acc.y);
        __half2 h1 = __floats2half2_rn(acc.z, acc.w);
        uint2 pk = make_uint2(*(uint32_t*)&h0, *(uint32_t*)&h1);
        ((uint2*)outb)[node * 32 + lane] = pk;
    }
}

// ---------------- fused MLP: p = relu(A@W1^T + b1) @ W2^T --------------------
// A: [M,128] fp16; W1: [256,128] fp16; W2: [128,256] fp16; p: [M,128] fp16.
// Block = 128 rows, 256 threads (8 warps 4x2). h block staged in smem fp16.
__device__ __forceinline__ void mma_f16(float c[4], const uint32_t a[4],
                                        const uint32_t b[2]) {
    asm volatile(
        "mma.sync.aligned.m16n8k16.row.col.f32.f16.f16.f32 "
        "{%0,%1,%2,%3}, {%4,%5,%6,%7}, {%8,%9}, {%0,%1,%2,%3};"
        : "+f"(c[0]), "+f"(c[1]), "+f"(c[2]), "+f"(c[3])
        : "r"(a[0]), "r"(a[1]), "r"(a[2]), "r"(a[3]), "r"(b[0]), "r"(b[1]));
}

#define AS_ST 68    // uints per row (64 data + 4 pad): 128-half rows
#define W2_ST 132   // uints per row (128 data + 4 pad): 256-half rows
#define SM_A  0                         // A_s:  128*68  = 8704 uints
#define SM_W  (SM_A + 128 * AS_ST)      // W_s:  128*132 = 16896 uints (phase1 uses 68-stride region semantics? no: phase1 W uses AS_ST inside this buffer)
#define SM_H  (SM_W + 128 * W2_ST)      // h_s:  128*132 = 16896 uints
#define SM_TOTAL_U (SM_H + 128 * W2_ST)

__global__ __launch_bounds__(256, 1)
void fused_mlp_kernel(const __half* __restrict__ A,
                      const __half* __restrict__ W1,
                      const __half* __restrict__ W2,
                      const float* __restrict__ b1,
                      __half* __restrict__ P, int M) {
    extern __shared__ uint32_t sm[];
    uint32_t* A_s = sm + SM_A;
    uint32_t* W_s = sm + SM_W;
    uint32_t* H_s = sm + SM_H;

    const int tid  = threadIdx.x;
    const int lane = tid & 31;
    const int warp = tid >> 5;
    const int wm   = warp & 3;        // m offset wm*32
    const int wn   = warp >> 2;       // n offset wn*64
    const int gid  = lane >> 2;       // 0..7
    const int tig  = lane & 3;        // 0..3
    const int m0   = blockIdx.x * 128;

    // ---- load A tile [128 x 128 halfs], stride AS_ST ----
#pragma unroll
    for (int l = 0; l < 8; l++) {
        int idx = tid + l * 256;      // 0..2047
        int row = idx >> 4;           // 0..127
        int q   = idx & 15;           // uint4 slot (8 halfs each)
        uint4 v = (m0 + row < M)
                ? *(const uint4*)(A + (size_t)(m0 + row) * DIN + q * 8)
                : make_uint4(0u, 0u, 0u, 0u);
        *(uint4*)&A_s[row * AS_ST + q * 4] = v;
    }

    // ---- phase 1: two 128-wide halves of h = relu(A@W1^T + b1) ----
    for (int nh = 0; nh < 2; nh++) {
        // load W1 rows [nh*128, +128), each 128 halfs, stride AS_ST
#pragma unroll
        for (int l = 0; l < 8; l++) {
            int idx = tid + l * 256;
            int row = idx >> 4;
            int q   = idx & 15;
            uint4 v = *(const uint4*)(W1 + (size_t)(nh * 128 + row) * DIN + q * 8);
            *(uint4*)&W_s[row * AS_ST + q * 4] = v;
        }
        __syncthreads();

        float acc[2][8][4];
#pragma unroll
        for (int i = 0; i < 2; i++)
#pragma unroll
            for (int j = 0; j < 8; j++)
#pragma unroll
                for (int q = 0; q < 4; q++) acc[i][j][q] = 0.f;

#pragma unroll
        for (int s = 0; s < 8; s++) {            // K=128 -> 8 k16 steps
            const int k2 = s * 8;
            uint32_t af[2][4];
#pragma unroll
            for (int mt = 0; mt < 2; mt++) {
                int rb = wm * 32 + mt * 16;
                af[mt][0] = A_s[(rb + gid) * AS_ST + k2 + tig];
                af[mt][1] = A_s[(rb + gid + 8) * AS_ST + k2 + tig];
                af[mt][2] = A_s[(rb + gid) * AS_ST + k2 + tig + 4];
                af[mt][3] = A_s[(rb + gid + 8) * AS_ST + k2 + tig + 4];
            }
            uint32_t bf[8][2];
#pragma unroll
            for (int ntl = 0; ntl < 8; ntl++) {
                int col = wn * 64 + ntl * 8 + gid;
                bf[ntl][0] = W_s[col * AS_ST + k2 + tig];
                bf[ntl][1] = W_s[col * AS_ST + k2 + tig + 4];
            }
#pragma unroll
            for (int mt = 0; mt < 2; mt++)
#pragma unroll
                for (int ntl = 0; ntl < 8; ntl++)
                    mma_f16(acc[mt][ntl], af[mt], bf[ntl]);
        }
        __syncthreads();   // all W_s reads done before next overwrite

        // epilogue: +b1, relu -> H_s fp16 (row stride W2_ST uints, 256 halfs)
#pragma unroll
        for (int mt = 0; mt < 2; mt++) {
            int r0 = wm * 32 + mt * 16 + gid;
            int r1 = r0 + 8;
#pragma unroll
            for (int ntl = 0; ntl < 8; ntl++) {
                int colL = wn * 64 + ntl * 8 + tig * 2;
                int colG = nh * 128 + colL;
                float bx = b1[colG], by = b1[colG + 1];
                float2 v0 = make_float2(fmaxf(acc[mt][ntl][0] + bx, 0.f),
                                        fmaxf(acc[mt][ntl][1] + by, 0.f));
                float2 v1 = make_float2(fmaxf(acc[mt][ntl][2] + bx, 0.f),
                                        fmaxf(acc[mt][ntl][3] + by, 0.f));
                __half2 h0 = __floats2half2_rn(v0.x, v0.y);
                __half2 h1 = __floats2half2_rn(v1.x, v1.y);
                H_s[r0 * W2_ST + (colG >> 1)] = *(uint32_t*)&h0;
                H_s[r1 * W2_ST + (colG >> 1)] = *(uint32_t*)&h1;
            }
        }
    }

    // ---- load W2 [128 rows x 256 halfs], stride W2_ST ----
#pragma unroll
    for (int l = 0; l < 16; l++) {
        int idx = tid + l * 256;      // 0..4095
        int row = idx >> 5;           // 0..127
        int q   = idx & 31;           // uint4 slot
        uint4 v = *(const uint4*)(W2 + (size_t)row * DH + q * 8);
        *(uint4*)&W_s[row * W2_ST + q * 4] = v;
    }
    __syncthreads();   // H_s + W2 ready

    // ---- phase 2: p = h @ W2^T (K=256 -> 16 k16 steps) ----
    float acc2[2][8][4];
#pragma unroll
    for (int i = 0; i < 2; i++)
#pragma unroll
        for (int j = 0; j < 8; j++)
#pragma unroll
            for (int q = 0; q < 4; q++) acc2[i][j][q] = 0.f;

#pragma unroll
    for (int s = 0; s < 16; s++) {
        const int k2 = s * 8;
        uint32_t af[2][4];
#pragma unroll
        for (int mt = 0; mt < 2; mt++) {
            int rb = wm * 32 + mt * 16;
            af[mt][0] = H_s[(rb + gid) * W2_ST + k2 + tig];
            af[mt][1] = H_s[(rb + gid + 8) * W2_ST + k2 + tig];
            af[mt][2] = H_s[(rb + gid) * W2_ST + k2 + tig + 4];
            af[mt][3] = H_s[(rb + gid + 8) * W2_ST + k2 + tig + 4];
        }
        uint32_t bf[8][2];
#pragma unroll
        for (int ntl = 0; ntl < 8; ntl++) {
            int col = wn * 64 + ntl * 8 + gid;
            bf[ntl][0] = W_s[col * W2_ST + k2 + tig];
            bf[ntl][1] = W_s[col * W2_ST + k2 + tig + 4];
        }
#pragma unroll
        for (int mt = 0; mt < 2; mt++)
#pragma unroll
            for (int ntl = 0; ntl < 8; ntl++)
                mma_f16(acc2[mt][ntl], af[mt], bf[ntl]);
    }

    // ---- epilogue: p fp16 ----
#pragma unroll
    for (int mt = 0; mt < 2; mt++) {
        int row0 = m0 + wm * 32 + mt * 16 + gid;
        int row1 = row0 + 8;
#pragma unroll
        for (int ntl = 0; ntl < 8; ntl++) {
            int col = wn * 64 + ntl * 8 + tig * 2;
            __half2 h0 = __floats2half2_rn(acc2[mt][ntl][0], acc2[mt][ntl][1]);
            __half2 h1 = __floats2half2_rn(acc2[mt][ntl][2], acc2[mt][ntl][3]);
            if (row0 < M) *(__half2*)(P + (size_t)row0 * DIN + col) = h0;
            if (row1 < M) *(__half2*)(P + (size_t)row1 * DIN + col) = h1;
        }
    }
}

// -----------------------------------------------------------------------------
extern "C" void kernel_launch(void* const* d_in, const int* in_sizes, int n_in,
                              void* d_out, int out_size) {
    const float* x     = (const float*)d_in[0];
    const void*  ei    = d_in[1];
    const float* ew    = (const float*)d_in[2];
    const float* W1    = (const float*)d_in[3];
    const float* b1    = (const float*)d_in[4];
    const float* W2    = (const float*)d_in[5];
    const float* b2    = (const float*)d_in[6];
    const float* gamma = (const float*)d_in[7];
    const float* beta  = (const float*)d_in[8];
    float*       out   = (float*)d_out;

    float *dinv;
    __half *xh, *a1h, *ph, *w1h, *w2h;
    int *cnt, *rowstart, *cursor;
    int2 *csr;
    cudaGetSymbolAddress((void**)&dinv,     g_dinv);
    cudaGetSymbolAddress((void**)&xh,       g_xh);
    cudaGetSymbolAddress((void**)&a1h,      g_a1h);
    cudaGetSymbolAddress((void**)&ph,       g_ph);
    cudaGetSymbolAddress((void**)&w1h,      g_w1h);
    cudaGetSymbolAddress((void**)&w2h,      g_w2h);
    cudaGetSymbolAddress((void**)&cnt,      g_count);
    cudaGetSymbolAddress((void**)&rowstart, g_rowstart);
    cudaGetSymbolAddress((void**)&cursor,   g_cursor);
    cudaGetSymbolAddress((void**)&csr,      g_csr);

    const int n = NN, e = EE;
    const int smem_bytes = SM_TOTAL_U * 4;
    static bool attr_set = false;
    if (!attr_set) {
        cudaFuncSetAttribute(fused_mlp_kernel,
                             cudaFuncAttributeMaxDynamicSharedMemorySize,
                             smem_bytes);
        attr_set = true;
    }

    // 1. prep: zero scratch, detect dtype, x/W1/W2 -> fp16
    prep_kernel<<<1024, 256>>>((const int*)ei, x, W1, W2, dinv, cnt);

    // 2. weighted degree + counts (decode raw, no staging)
    convert_deg_kernel<<<(e + 255) / 256, 256>>>(ei, ew, dinv, cnt, e);

    // 3. single-pass scan (+dinv, cursor init)
    scan_lookback_kernel<<<NBLK, 256>>>(cnt, dinv, rowstart, cursor, n);

    // 4. CSR fill (re-decode raw)
    csr_fill_kernel<<<(e + 255) / 256, 256>>>(ei, ew, dinv, cursor, csr, e);

    // 5. agg1 = A_norm @ x  (fp16 gather -> fp16)
    gather_kernel<0><<<(n * 32 + 255) / 256, 256>>>(rowstart, csr, dinv, xh,
                                                    nullptr, nullptr, nullptr,
                                                    a1h, n);

    // 6. p = relu(agg1 @ W1^T + b1) @ W2^T   (fused MLP)
    fused_mlp_kernel<<<(n + 127) / 128, 256, smem_bytes>>>(a1h, w1h, w2h, b1,
                                                           ph, n);

    // 7. out = LN(A_norm @ p + b2) * gamma + beta
    gather_kernel<1><<<(n * 32 + 255) / 256, 256>>>(rowstart, csr, dinv, ph,
                                                    b2, gamma, beta, out, n);
}

// round 11
// speedup vs baseline: 3.0947x; 1.0191x over previous
#include <cuda_runtime.h>
#include <cuda_fp16.h>
#include <cstdint>
#include <cstddef>

#define NN   50000
#define EE   800000
#define DIN  128
#define DH   256
#define NBLK ((NN + 255) / 256)   // 196 scan blocks

// ---------------- scratch (device globals; no allocation allowed) ------------
__device__ float  g_dinv[NN];             // weighted in-degree -> rsqrt in place
__device__ int    g_count[NN];            // per-dst edge count
__device__ int    g_rowstart[NN + 1];     // CSR offsets
__device__ uint2  g_stage[EE];            // (src | dst<<16, rank)
__device__ int2   g_csr[EE];              // packed (src, nrm-as-bits)
__device__ __half g_xh[NN * DIN];         // x in fp16
__device__ __half g_a1h[NN * DIN];        // A @ x in fp16 (GEMM input)
__device__ __half g_ph[NN * DIN];         // fused-GEMM output in fp16
__device__ __half g_w1h[DH * DIN];        // W1 fp16
__device__ __half g_w2h[DIN * DH];        // W2 fp16
__device__ int    g_is64;
__device__ int    g_ticket;                        // lookback ticket
__device__ unsigned long long g_state[NBLK];       // value<<2 | flag

// ---------------- prep: zero scratch + dtype detect + fp16 conversions -------
__global__ void prep_kernel(const int* __restrict__ raw,
                            const float* __restrict__ x,
                            const float* __restrict__ W1,
                            const float* __restrict__ W2,
                            float* __restrict__ deg,
                            int* __restrict__ cnt) {
    const int gtid   = blockIdx.x * blockDim.x + threadIdx.x;
    const int stride = gridDim.x * blockDim.x;

    for (int i = gtid; i < NN; i += stride) { deg[i] = 0.f; cnt[i] = 0; }
    for (int i = gtid; i < NBLK; i += stride) g_state[i] = 0ull;
    if (gtid == 0) g_ticket = 0;

    const int pairs = NN * DIN / 2;
    const float2* xin = (const float2*)x;
    __half2* xo = (__half2*)g_xh;
    for (int i = gtid; i < pairs; i += stride) {
        float2 v = xin[i];
        xo[i] = __floats2half2_rn(v.x, v.y);
    }
    const int wp = DH * DIN / 2;
    const float2* w1in = (const float2*)W1;
    const float2* w2in = (const float2*)W2;
    __half2* w1o = (__half2*)g_w1h;
    __half2* w2o = (__half2*)g_w2h;
    for (int i = gtid; i < wp; i += stride) {
        float2 a = w1in[i];
        float2 b = w2in[i];
        w1o[i] = __floats2half2_rn(a.x, a.y);
        w2o[i] = __floats2half2_rn(b.x, b.y);
    }

    if (blockIdx.x == 0) {
        int odd = (threadIdx.x < 128) ? raw[2 * threadIdx.x + 1] : 0;
        int any = __syncthreads_or(odd != 0);
        if (threadIdx.x == 0) g_is64 = any ? 0 : 1;
    }
}

// ---------------- index decode helper ----------------------------------------
__device__ __forceinline__ void decode_edge(const void* raw, int e, int i,
                                            int& s, int& d) {
    if (g_is64) {
        const long long* p = (const long long*)raw;
        s = (int)p[i];
        d = (int)p[(size_t)e + i];
    } else {
        const int* p = (const int*)raw;
        s = p[i];
        d = p[e + i];
    }
}

// ------- degree/counts + stage (src,dst,rank); rank = slot within dst --------
__global__ void convert_deg_kernel(const void* __restrict__ raw,
                                   const float* __restrict__ w,
                                   float* __restrict__ deg,
                                   int* __restrict__ cnt,
                                   uint2* __restrict__ stage, int e) {
    int i = blockIdx.x * blockDim.x + threadIdx.x;
    if (i >= e) return;
    int s, d;
    decode_edge(raw, e, i, s, d);
    atomicAdd(&deg[d], w[i]);
    int rank = atomicAdd(&cnt[d], 1);
    stage[i] = make_uint2((unsigned)s | ((unsigned)d << 16), (unsigned)rank);
}

// ---------------- single-pass lookback scan (+dinv fused) --------------------
__device__ __forceinline__ int block_scan_incl(int v) {
    const int lane = threadIdx.x & 31;
    const int warp = threadIdx.x >> 5;
    int s = v;
#pragma unroll
    for (int o = 1; o < 32; o <<= 1) {
        int t = __shfl_up_sync(0xFFFFFFFFu, s, o);
        if (lane >= o) s += t;
    }
    __shared__ int wsum[8];
    if (lane == 31) wsum[warp] = s;
    __syncthreads();
    if (warp == 0 && lane < 8) {
        int ws = wsum[lane];
#pragma unroll
        for (int o = 1; o < 8; o <<= 1) {
            int t = __shfl_up_sync(0xFFu, ws, o);
            if (lane >= o) ws += t;
        }
        wsum[lane] = ws;
    }
    __syncthreads();
    return s + (warp > 0 ? wsum[warp - 1] : 0);
}

__global__ void scan_lookback_kernel(const int* __restrict__ cnt,
                                     float* __restrict__ deg,   // -> dinv
                                     int* __restrict__ rowstart, int n) {
    __shared__ int s_bid, s_total, s_excl;
    if (threadIdx.x == 0) s_bid = atomicAdd(&g_ticket, 1);
    __syncthreads();
    const int bid = s_bid;
    const int idx = bid * 256 + threadIdx.x;

    int v = (idx < n) ? cnt[idx] : 0;
    int incl = block_scan_incl(v);
    if (threadIdx.x == 255) s_total = incl;
    __syncthreads();

    if (threadIdx.x == 0) {
        volatile unsigned long long* st = g_state;
        unsigned long long pkt =
            ((unsigned long long)s_total << 2) | (bid == 0 ? 2ull : 1ull);
        __threadfence();
        st[bid] = pkt;
        int excl = 0;
        if (bid > 0) {
            int j = bid - 1;
            while (true) {
                unsigned long long sv = st[j];
                unsigned f = (unsigned)(sv & 3ull);
                if (f == 0) continue;
                excl += (int)(sv >> 2);
                if (f == 2) break;
                j--;
            }
            unsigned long long pkt2 =
                ((unsigned long long)(excl + s_total) << 2) | 2ull;
            __threadfence();
            st[bid] = pkt2;
        }
        s_excl = excl;
    }
    __syncthreads();

    const int base = s_excl;
    if (idx < n) {
        rowstart[idx] = base + incl - v;
        deg[idx] = rsqrtf(deg[idx] + 1.0f);   // dinv fused (+1 = self-loop)
    }
    if (bid == (n + 255) / 256 - 1 && threadIdx.x == 255)
        rowstart[n] = base + s_total;
}

// ---------------- CSR fill: pos = rowstart[d] + rank (no atomics) ------------
__global__ void csr_fill_kernel(const uint2* __restrict__ stage,
                                const float* __restrict__ w,
                                const float* __restrict__ dinv,
                                const int* __restrict__ rowstart,
                                int2* __restrict__ csr, int e) {
    int i = blockIdx.x * blockDim.x + threadIdx.x;
    if (i >= e) return;
    uint2 st = stage[i];
    int s = (int)(st.x & 0xFFFFu);
    int d = (int)(st.x >> 16);
    float nrm = dinv[s] * w[i] * dinv[d];
    int pos = rowstart[d] + (int)st.y;
    csr[pos] = make_int2(s, __float_as_int(nrm));
}

// ---------------- CSR gather over fp16 features, fp32 accumulate -------------
__device__ __forceinline__ float4 h4_to_f4(uint2 u) {
    __half2 a = *(__half2*)&u.x;
    __half2 b = *(__half2*)&u.y;
    float2 fa = __half22float2(a);
    float2 fb = __half22float2(b);
    return make_float4(fa.x, fa.y, fb.x, fb.y);
}

// DO_LN=0: write fp16 (outb = __half*). DO_LN=1: LN, write fp32 (outb = float*)
template <int DO_LN>
__global__ __launch_bounds__(256)
void gather_kernel(const int* __restrict__ rowstart,
                   const int2* __restrict__ csr,
                   const float* __restrict__ dinv,
                   const __half* __restrict__ feat,
                   const float* __restrict__ b2,
                   const float* __restrict__ gamma,
                   const float* __restrict__ beta,
                   void* __restrict__ outb, int n) {
    const int node = (blockIdx.x * blockDim.x + threadIdx.x) >> 5;
    const int lane = threadIdx.x & 31;
    if (node >= n) return;

    const uint2* fp = (const uint2*)feat;   // row = 32 uint2
    float dv = dinv[node];
    float4 acc = h4_to_f4(fp[node * 32 + lane]);
    acc.x *= dv * dv; acc.y *= dv * dv; acc.z *= dv * dv; acc.w *= dv * dv;

    const int beg = rowstart[node];
    const int end = rowstart[node + 1];

    int j = beg;
    for (; j + 3 < end; j += 4) {
        int2 e0 = csr[j], e1 = csr[j + 1], e2 = csr[j + 2], e3 = csr[j + 3];
        uint2 r0 = fp[e0.x * 32 + lane];
        uint2 r1 = fp[e1.x * 32 + lane];
        uint2 r2 = fp[e2.x * 32 + lane];
        uint2 r3 = fp[e3.x * 32 + lane];
        float4 v0 = h4_to_f4(r0), v1 = h4_to_f4(r1);
        float4 v2 = h4_to_f4(r2), v3 = h4_to_f4(r3);
        float n0 = __int_as_float(e0.y), n1 = __int_as_float(e1.y);
        float n2 = __int_as_float(e2.y), n3 = __int_as_float(e3.y);
        acc.x = fmaf(v0.x, n0, acc.x); acc.y = fmaf(v0.y, n0, acc.y);
        acc.z = fmaf(v0.z, n0, acc.z); acc.w = fmaf(v0.w, n0, acc.w);
        acc.x = fmaf(v1.x, n1, acc.x); acc.y = fmaf(v1.y, n1, acc.y);
        acc.z = fmaf(v1.z, n1, acc.z); acc.w = fmaf(v1.w, n1, acc.w);
        acc.x = fmaf(v2.x, n2, acc.x); acc.y = fmaf(v2.y, n2, acc.y);
        acc.z = fmaf(v2.z, n2, acc.z); acc.w = fmaf(v2.w, n2, acc.w);
        acc.x = fmaf(v3.x, n3, acc.x); acc.y = fmaf(v3.y, n3, acc.y);
        acc.z = fmaf(v3.z, n3, acc.z); acc.w = fmaf(v3.w, n3, acc.w);
    }
    for (; j < end; j++) {
        int2 e0 = csr[j];
        float4 v0 = h4_to_f4(fp[e0.x * 32 + lane]);
        float n0 = __int_as_float(e0.y);
        acc.x = fmaf(v0.x, n0, acc.x); acc.y = fmaf(v0.y, n0, acc.y);
        acc.z = fmaf(v0.z, n0, acc.z); acc.w = fmaf(v0.w, n0, acc.w);
    }

    if (DO_LN) {
        float4 bb = *(const float4*)(b2 + lane * 4);
        acc.x += bb.x; acc.y += bb.y; acc.z += bb.z; acc.w += bb.w;

        float s = acc.x + acc.y + acc.z + acc.w;
#pragma unroll
        for (int o = 16; o > 0; o >>= 1) s += __shfl_xor_sync(0xFFFFFFFFu, s, o);
        float mu = s * (1.0f / DIN);

        float dx = acc.x - mu, dy = acc.y - mu, dz = acc.z - mu, dw = acc.w - mu;
        float q = dx * dx + dy * dy + dz * dz + dw * dw;
#pragma unroll
        for (int o = 16; o > 0; o >>= 1) q += __shfl_xor_sync(0xFFFFFFFFu, q, o);
        float rstd = rsqrtf(q * (1.0f / DIN) + 1e-5f);

        float4 g  = *(const float4*)(gamma + lane * 4);
        float4 bt = *(const float4*)(beta + lane * 4);
        float4 o4;
        o4.x = dx * rstd * g.x + bt.x;
        o4.y = dy * rstd * g.y + bt.y;
        o4.z = dz * rstd * g.z + bt.z;
        o4.w = dw * rstd * g.w + bt.w;
        *(float4*)((float*)outb + (size_t)node * DIN + lane * 4) = o4;
    } else {
        __half2 h0 = __floats2half2_rn(acc.x, acc.y);
        __half2 h1 = __floats2half2_rn(acc.z, acc.w);
        uint2 pk = make_uint2(*(uint32_t*)&h0, *(uint32_t*)&h1);
        ((uint2*)outb)[node * 32 + lane] = pk;
    }
}

// ---------------- fused MLP: p = relu(A@W1^T + b1) @ W2^T --------------------
__device__ __forceinline__ void mma_f16(float c[4], const uint32_t a[4],
                                        const uint32_t b[2]) {
    asm volatile(
        "mma.sync.aligned.m16n8k16.row.col.f32.f16.f16.f32 "
        "{%0,%1,%2,%3}, {%4,%5,%6,%7}, {%8,%9}, {%0,%1,%2,%3};"
        : "+f"(c[0]), "+f"(c[1]), "+f"(c[2]), "+f"(c[3])
        : "r"(a[0]), "r"(a[1]), "r"(a[2]), "r"(a[3]), "r"(b[0]), "r"(b[1]));
}

#define AS_ST 68    // uints per row (64 data + 4 pad): 128-half rows
#define W2_ST 132   // uints per row (128 data + 4 pad): 256-half rows
#define SM_A  0
#define SM_W  (SM_A + 128 * AS_ST)
#define SM_H  (SM_W + 128 * W2_ST)
#define SM_TOTAL_U (SM_H + 128 * W2_ST)

__global__ __launch_bounds__(256, 1)
void fused_mlp_kernel(const __half* __restrict__ A,
                      const __half* __restrict__ W1,
                      const __half* __restrict__ W2,
                      const float* __restrict__ b1,
                      __half* __restrict__ P, int M) {
    extern __shared__ uint32_t sm[];
    uint32_t* A_s = sm + SM_A;
    uint32_t* W_s = sm + SM_W;
    uint32_t* H_s = sm + SM_H;

    const int tid  = threadIdx.x;
    const int lane = tid & 31;
    const int warp = tid >> 5;
    const int wm   = warp & 3;
    const int wn   = warp >> 2;
    const int gid  = lane >> 2;
    const int tig  = lane & 3;
    const int m0   = blockIdx.x * 128;

#pragma unroll
    for (int l = 0; l < 8; l++) {
        int idx = tid + l * 256;
        int row = idx >> 4;
        int q   = idx & 15;
        uint4 v = (m0 + row < M)
                ? *(const uint4*)(A + (size_t)(m0 + row) * DIN + q * 8)
                : make_uint4(0u, 0u, 0u, 0u);
        *(uint4*)&A_s[row * AS_ST + q * 4] = v;
    }

    for (int nh = 0; nh < 2; nh++) {
#pragma unroll
        for (int l = 0; l < 8; l++) {
            int idx = tid + l * 256;
            int row = idx >> 4;
            int q   = idx & 15;
            uint4 v = *(const uint4*)(W1 + (size_t)(nh * 128 + row) * DIN + q * 8);
            *(uint4*)&W_s[row * AS_ST + q * 4] = v;
        }
        __syncthreads();

        float acc[2][8][4];
#pragma unroll
        for (int i = 0; i < 2; i++)
#pragma unroll
            for (int j = 0; j < 8; j++)
#pragma unroll
                for (int q = 0; q < 4; q++) acc[i][j][q] = 0.f;

#pragma unroll
        for (int s = 0; s < 8; s++) {
            const int k2 = s * 8;
            uint32_t af[2][4];
#pragma unroll
            for (int mt = 0; mt < 2; mt++) {
                int rb = wm * 32 + mt * 16;
                af[mt][0] = A_s[(rb + gid) * AS_ST + k2 + tig];
                af[mt][1] = A_s[(rb + gid + 8) * AS_ST + k2 + tig];
                af[mt][2] = A_s[(rb + gid) * AS_ST + k2 + tig + 4];
                af[mt][3] = A_s[(rb + gid + 8) * AS_ST + k2 + tig + 4];
            }
            uint32_t bf[8][2];
#pragma unroll
            for (int ntl = 0; ntl < 8; ntl++) {
                int col = wn * 64 + ntl * 8 + gid;
                bf[ntl][0] = W_s[col * AS_ST + k2 + tig];
                bf[ntl][1] = W_s[col * AS_ST + k2 + tig + 4];
            }
#pragma unroll
            for (int mt = 0; mt < 2; mt++)
#pragma unroll
                for (int ntl = 0; ntl < 8; ntl++)
                    mma_f16(acc[mt][ntl], af[mt], bf[ntl]);
        }
        __syncthreads();

#pragma unroll
        for (int mt = 0; mt < 2; mt++) {
            int r0 = wm * 32 + mt * 16 + gid;
            int r1 = r0 + 8;
#pragma unroll
            for (int ntl = 0; ntl < 8; ntl++) {
                int colL = wn * 64 + ntl * 8 + tig * 2;
                int colG = nh * 128 + colL;
                float bx = b1[colG], by = b1[colG + 1];
                float2 v0 = make_float2(fmaxf(acc[mt][ntl][0] + bx, 0.f),
                                        fmaxf(acc[mt][ntl][1] + by, 0.f));
                float2 v1 = make_float2(fmaxf(acc[mt][ntl][2] + bx, 0.f),
                                        fmaxf(acc[mt][ntl][3] + by, 0.f));
                __half2 h0 = __floats2half2_rn(v0.x, v0.y);
                __half2 h1 = __floats2half2_rn(v1.x, v1.y);
                H_s[r0 * W2_ST + (colG >> 1)] = *(uint32_t*)&h0;
                H_s[r1 * W2_ST + (colG >> 1)] = *(uint32_t*)&h1;
            }
        }
    }

#pragma unroll
    for (int l = 0; l < 16; l++) {
        int idx = tid + l * 256;
        int row = idx >> 5;
        int q   = idx & 31;
        uint4 v = *(const uint4*)(W2 + (size_t)row * DH + q * 8);
        *(uint4*)&W_s[row * W2_ST + q * 4] = v;
    }
    __syncthreads();

    float acc2[2][8][4];
#pragma unroll
    for (int i = 0; i < 2; i++)
#pragma unroll
        for (int j = 0; j < 8; j++)
#pragma unroll
            for (int q = 0; q < 4; q++) acc2[i][j][q] = 0.f;

#pragma unroll
    for (int s = 0; s < 16; s++) {
        const int k2 = s * 8;
        uint32_t af[2][4];
#pragma unroll
        for (int mt = 0; mt < 2; mt++) {
            int rb = wm * 32 + mt * 16;
            af[mt][0] = H_s[(rb + gid) * W2_ST + k2 + tig];
            af[mt][1] = H_s[(rb + gid + 8) * W2_ST + k2 + tig];
            af[mt][2] = H_s[(rb + gid) * W2_ST + k2 + tig + 4];
            af[mt][3] = H_s[(rb + gid + 8) * W2_ST + k2 + tig + 4];
        }
        uint32_t bf[8][2];
#pragma unroll
        for (int ntl = 0; ntl < 8; ntl++) {
            int col = wn * 64 + ntl * 8 + gid;
            bf[ntl][0] = W_s[col * W2_ST + k2 + tig];
            bf[ntl][1] = W_s[col * W2_ST + k2 + tig + 4];
        }
#pragma unroll
        for (int mt = 0; mt < 2; mt++)
#pragma unroll
            for (int ntl = 0; ntl < 8; ntl++)
                mma_f16(acc2[mt][ntl], af[mt], bf[ntl]);
    }

#pragma unroll
    for (int mt = 0; mt < 2; mt++) {
        int row0 = m0 + wm * 32 + mt * 16 + gid;
        int row1 = row0 + 8;
#pragma unroll
        for (int ntl = 0; ntl < 8; ntl++) {
            int col = wn * 64 + ntl * 8 + tig * 2;
            __half2 h0 = __floats2half2_rn(acc2[mt][ntl][0], acc2[mt][ntl][1]);
            __half2 h1 = __floats2half2_rn(acc2[mt][ntl][2], acc2[mt][ntl][3]);
            if (row0 < M) *(__half2*)(P + (size_t)row0 * DIN + col) = h0;
            if (row1 < M) *(__half2*)(P + (size_t)row1 * DIN + col) = h1;
        }
    }
}

// -----------------------------------------------------------------------------
extern "C" void kernel_launch(void* const* d_in, const int* in_sizes, int n_in,
                              void* d_out, int out_size) {
    const float* x     = (const float*)d_in[0];
    const void*  ei    = d_in[1];
    const float* ew    = (const float*)d_in[2];
    const float* W1    = (const float*)d_in[3];
    const float* b1    = (const float*)d_in[4];
    const float* W2    = (const float*)d_in[5];
    const float* b2    = (const float*)d_in[6];
    const float* gamma = (const float*)d_in[7];
    const float* beta  = (const float*)d_in[8];
    float*       out   = (float*)d_out;

    float *dinv;
    __half *xh, *a1h, *ph, *w1h, *w2h;
    int *cnt, *rowstart;
    uint2 *stage;
    int2 *csr;
    cudaGetSymbolAddress((void**)&dinv,     g_dinv);
    cudaGetSymbolAddress((void**)&xh,       g_xh);
    cudaGetSymbolAddress((void**)&a1h,      g_a1h);
    cudaGetSymbolAddress((void**)&ph,       g_ph);
    cudaGetSymbolAddress((void**)&w1h,      g_w1h);
    cudaGetSymbolAddress((void**)&w2h,      g_w2h);
    cudaGetSymbolAddress((void**)&cnt,      g_count);
    cudaGetSymbolAddress((void**)&rowstart, g_rowstart);
    cudaGetSymbolAddress((void**)&stage,    g_stage);
    cudaGetSymbolAddress((void**)&csr,      g_csr);

    const int n = NN, e = EE;
    const int smem_bytes = SM_TOTAL_U * 4;
    static bool attr_set = false;
    if (!attr_set) {
        cudaFuncSetAttribute(fused_mlp_kernel,
                             cudaFuncAttributeMaxDynamicSharedMemorySize,
                             smem_bytes);
        attr_set = true;
    }

    // 1. prep: zero scratch, detect dtype, x/W1/W2 -> fp16
    prep_kernel<<<1024, 256>>>((const int*)ei, x, W1, W2, dinv, cnt);

    // 2. degree + counts + stage (src,dst,rank)
    convert_deg_kernel<<<(e + 255) / 256, 256>>>(ei, ew, dinv, cnt, stage, e);

    // 3. single-pass scan (+dinv)
    scan_lookback_kernel<<<NBLK, 256>>>(cnt, dinv, rowstart, n);

    // 4. CSR fill: pos = rowstart + rank (atomic-free)
    csr_fill_kernel<<<(e + 255) / 256, 256>>>(stage, ew, dinv, rowstart, csr, e);

    // 5. agg1 = A_norm @ x  (fp16 gather -> fp16)
    gather_kernel<0><<<(n * 32 + 255) / 256, 256>>>(rowstart, csr, dinv, xh,
                                                    nullptr, nullptr, nullptr,
                                                    a1h, n);

    // 6. p = relu(agg1 @ W1^T + b1) @ W2^T   (fused MLP)
    fused_mlp_kernel<<<(n + 127) / 128, 256, smem_bytes>>>(a1h, w1h, w2h, b1,
                                                           ph, n);

    // 7. out = LN(A_norm @ p + b2) * gamma + beta
    gather_kernel<1><<<(n * 32 + 255) / 256, 256>>>(rowstart, csr, dinv, ph,
                                                    b2, gamma, beta, out, n);
}

// round 12
// speedup vs baseline: 3.1878x; 1.0301x over previous
#include <cuda_runtime.h>
#include <cuda_fp16.h>
#include <cstdint>
#include <cstddef>

#define NN   50000
#define EE   800000
#define DIN  128
#define DH   256
#define NBLK ((NN + 255) / 256)   // 196 scan blocks

// ---------------- scratch (device globals; no allocation allowed) ------------
__device__ float  g_dinv[NN];             // weighted in-degree -> rsqrt in place
__device__ int    g_count[NN];            // per-dst edge count
__device__ int    g_rowstart[NN + 1];     // CSR offsets
__device__ uint2  g_stage[EE];            // (src | dst<<16, rank)
__device__ int2   g_csr[EE];              // packed (src, w*dinv[s] as bits)
__device__ __half g_xh[NN * DIN];         // x in fp16
__device__ __half g_a1h[NN * DIN];        // A @ x in fp16 (GEMM input)
__device__ __half g_ph[NN * DIN];         // fused-GEMM output in fp16
__device__ __half g_w1h[DH * DIN];        // W1 fp16
__device__ __half g_w2h[DIN * DH];        // W2 fp16
__device__ int    g_is64;
__device__ int    g_ticket;                        // lookback ticket
__device__ unsigned long long g_state[NBLK];       // value<<2 | flag

// ---------------- prep: zero scratch + dtype detect + fp16 conversions -------
__global__ void prep_kernel(const int* __restrict__ raw,
                            const float* __restrict__ x,
                            const float* __restrict__ W1,
                            const float* __restrict__ W2,
                            float* __restrict__ deg,
                            int* __restrict__ cnt) {
    const int gtid   = blockIdx.x * blockDim.x + threadIdx.x;
    const int stride = gridDim.x * blockDim.x;

    for (int i = gtid; i < NN; i += stride) { deg[i] = 0.f; cnt[i] = 0; }
    for (int i = gtid; i < NBLK; i += stride) g_state[i] = 0ull;
    if (gtid == 0) g_ticket = 0;

    const int pairs = NN * DIN / 2;
    const float2* xin = (const float2*)x;
    __half2* xo = (__half2*)g_xh;
    for (int i = gtid; i < pairs; i += stride) {
        float2 v = xin[i];
        xo[i] = __floats2half2_rn(v.x, v.y);
    }
    const int wp = DH * DIN / 2;
    const float2* w1in = (const float2*)W1;
    const float2* w2in = (const float2*)W2;
    __half2* w1o = (__half2*)g_w1h;
    __half2* w2o = (__half2*)g_w2h;
    for (int i = gtid; i < wp; i += stride) {
        float2 a = w1in[i];
        float2 b = w2in[i];
        w1o[i] = __floats2half2_rn(a.x, a.y);
        w2o[i] = __floats2half2_rn(b.x, b.y);
    }

    if (blockIdx.x == 0) {
        int odd = (threadIdx.x < 128) ? raw[2 * threadIdx.x + 1] : 0;
        int any = __syncthreads_or(odd != 0);
        if (threadIdx.x == 0) g_is64 = any ? 0 : 1;
    }
}

// ---------------- index decode helper ----------------------------------------
__device__ __forceinline__ void decode_edge(const void* raw, int e, int i,
                                            int& s, int& d) {
    if (g_is64) {
        const long long* p = (const long long*)raw;
        s = (int)p[i];
        d = (int)p[(size_t)e + i];
    } else {
        const int* p = (const int*)raw;
        s = p[i];
        d = p[e + i];
    }
}

// ------- degree/counts + stage (src,dst,rank); 2 edges per thread ------------
__global__ void convert_deg_kernel(const void* __restrict__ raw,
                                   const float* __restrict__ w,
                                   float* __restrict__ deg,
                                   int* __restrict__ cnt,
                                   uint2* __restrict__ stage, int e) {
    int base = (blockIdx.x * blockDim.x + threadIdx.x) * 2;
    if (base >= e) return;
    int s0, d0, s1 = 0, d1 = 0;
    decode_edge(raw, e, base, s0, d0);
    bool two = (base + 1 < e);
    if (two) decode_edge(raw, e, base + 1, s1, d1);
    float w0 = w[base];
    float w1 = two ? w[base + 1] : 0.f;

    atomicAdd(&deg[d0], w0);
    int r0 = atomicAdd(&cnt[d0], 1);
    stage[base] = make_uint2((unsigned)s0 | ((unsigned)d0 << 16), (unsigned)r0);
    if (two) {
        atomicAdd(&deg[d1], w1);
        int r1 = atomicAdd(&cnt[d1], 1);
        stage[base + 1] =
            make_uint2((unsigned)s1 | ((unsigned)d1 << 16), (unsigned)r1);
    }
}

// ---------------- single-pass lookback scan (+dinv fused) --------------------
__device__ __forceinline__ int block_scan_incl(int v) {
    const int lane = threadIdx.x & 31;
    const int warp = threadIdx.x >> 5;
    int s = v;
#pragma unroll
    for (int o = 1; o < 32; o <<= 1) {
        int t = __shfl_up_sync(0xFFFFFFFFu, s, o);
        if (lane >= o) s += t;
    }
    __shared__ int wsum[8];
    if (lane == 31) wsum[warp] = s;
    __syncthreads();
    if (warp == 0 && lane < 8) {
        int ws = wsum[lane];
#pragma unroll
        for (int o = 1; o < 8; o <<= 1) {
            int t = __shfl_up_sync(0xFFu, ws, o);
            if (lane >= o) ws += t;
        }
        wsum[lane] = ws;
    }
    __syncthreads();
    return s + (warp > 0 ? wsum[warp - 1] : 0);
}

__global__ void scan_lookback_kernel(const int* __restrict__ cnt,
                                     float* __restrict__ deg,   // -> dinv
                                     int* __restrict__ rowstart, int n) {
    __shared__ int s_bid, s_total, s_excl;
    if (threadIdx.x == 0) s_bid = atomicAdd(&g_ticket, 1);
    __syncthreads();
    const int bid = s_bid;
    const int idx = bid * 256 + threadIdx.x;

    int v = (idx < n) ? cnt[idx] : 0;
    int incl = block_scan_incl(v);
    if (threadIdx.x == 255) s_total = incl;
    __syncthreads();

    if (threadIdx.x == 0) {
        volatile unsigned long long* st = g_state;
        unsigned long long pkt =
            ((unsigned long long)s_total << 2) | (bid == 0 ? 2ull : 1ull);
        __threadfence();
        st[bid] = pkt;
        int excl = 0;
        if (bid > 0) {
            int j = bid - 1;
            while (true) {
                unsigned long long sv = st[j];
                unsigned f = (unsigned)(sv & 3ull);
                if (f == 0) continue;
                excl += (int)(sv >> 2);
                if (f == 2) break;
                j--;
            }
            unsigned long long pkt2 =
                ((unsigned long long)(excl + s_total) << 2) | 2ull;
            __threadfence();
            st[bid] = pkt2;
        }
        s_excl = excl;
    }
    __syncthreads();

    const int base = s_excl;
    if (idx < n) {
        rowstart[idx] = base + incl - v;
        deg[idx] = rsqrtf(deg[idx] + 1.0f);   // dinv fused (+1 = self-loop)
    }
    if (bid == (n + 255) / 256 - 1 && threadIdx.x == 255)
        rowstart[n] = base + s_total;
}

// --------- CSR fill: pos = rowstart[d] + rank; store (s, w*dinv[s]) ----------
// dinv[d] factored out of the sum -> applied once in gather.
__global__ void csr_fill_kernel(const uint2* __restrict__ stage,
                                const float* __restrict__ w,
                                const float* __restrict__ dinv,
                                const int* __restrict__ rowstart,
                                int2* __restrict__ csr, int e) {
    int base = (blockIdx.x * blockDim.x + threadIdx.x) * 2;
    if (base >= e) return;
    // batched loads
    uint2 st0 = stage[base];
    bool two = (base + 1 < e);
    uint2 st1 = two ? stage[base + 1] : make_uint2(0u, 0u);
    float w0 = w[base];
    float w1 = two ? w[base + 1] : 0.f;

    int s0 = (int)(st0.x & 0xFFFFu), d0 = (int)(st0.x >> 16);
    int s1 = (int)(st1.x & 0xFFFFu), d1 = (int)(st1.x >> 16);
    float ds0 = dinv[s0];
    float ds1 = two ? dinv[s1] : 0.f;
    int rs0 = rowstart[d0];
    int rs1 = two ? rowstart[d1] : 0;

    csr[rs0 + (int)st0.y] = make_int2(s0, __float_as_int(w0 * ds0));
    if (two)
        csr[rs1 + (int)st1.y] = make_int2(s1, __float_as_int(w1 * ds1));
}

// ---------------- CSR gather over fp16 features, fp32 accumulate -------------
__device__ __forceinline__ float4 h4_to_f4(uint2 u) {
    __half2 a = *(__half2*)&u.x;
    __half2 b = *(__half2*)&u.y;
    float2 fa = __half22float2(a);
    float2 fb = __half22float2(b);
    return make_float4(fa.x, fa.y, fb.x, fb.y);
}

// DO_LN=0: write fp16 (outb = __half*). DO_LN=1: LN, write fp32 (outb = float*)
template <int DO_LN>
__global__ __launch_bounds__(256)
void gather_kernel(const int* __restrict__ rowstart,
                   const int2* __restrict__ csr,
                   const float* __restrict__ dinv,
                   const __half* __restrict__ feat,
                   const float* __restrict__ b2,
                   const float* __restrict__ gamma,
                   const float* __restrict__ beta,
                   void* __restrict__ outb, int n) {
    const int node = (blockIdx.x * blockDim.x + threadIdx.x) >> 5;
    const int lane = threadIdx.x & 31;
    if (node >= n) return;

    const uint2* fp = (const uint2*)feat;   // row = 32 uint2
    float dv = dinv[node];
    // acc = dv*x[node] + sum w'_e * x[s_e];  final acc *= dv
    float4 acc = h4_to_f4(fp[node * 32 + lane]);
    acc.x *= dv; acc.y *= dv; acc.z *= dv; acc.w *= dv;

    const int beg = rowstart[node];
    const int end = rowstart[node + 1];

    int j = beg;
    for (; j + 3 < end; j += 4) {
        int2 e0 = csr[j], e1 = csr[j + 1], e2 = csr[j + 2], e3 = csr[j + 3];
        uint2 r0 = fp[e0.x * 32 + lane];
        uint2 r1 = fp[e1.x * 32 + lane];
        uint2 r2 = fp[e2.x * 32 + lane];
        uint2 r3 = fp[e3.x * 32 + lane];
        float4 v0 = h4_to_f4(r0), v1 = h4_to_f4(r1);
        float4 v2 = h4_to_f4(r2), v3 = h4_to_f4(r3);
        float n0 = __int_as_float(e0.y), n1 = __int_as_float(e1.y);
        float n2 = __int_as_float(e2.y), n3 = __int_as_float(e3.y);
        acc.x = fmaf(v0.x, n0, acc.x); acc.y = fmaf(v0.y, n0, acc.y);
        acc.z = fmaf(v0.z, n0, acc.z); acc.w = fmaf(v0.w, n0, acc.w);
        acc.x = fmaf(v1.x, n1, acc.x); acc.y = fmaf(v1.y, n1, acc.y);
        acc.z = fmaf(v1.z, n1, acc.z); acc.w = fmaf(v1.w, n1, acc.w);
        acc.x = fmaf(v2.x, n2, acc.x); acc.y = fmaf(v2.y, n2, acc.y);
        acc.z = fmaf(v2.z, n2, acc.z); acc.w = fmaf(v2.w, n2, acc.w);
        acc.x = fmaf(v3.x, n3, acc.x); acc.y = fmaf(v3.y, n3, acc.y);
        acc.z = fmaf(v3.z, n3, acc.z); acc.w = fmaf(v3.w, n3, acc.w);
    }
    for (; j < end; j++) {
        int2 e0 = csr[j];
        float4 v0 = h4_to_f4(fp[e0.x * 32 + lane]);
        float n0 = __int_as_float(e0.y);
        acc.x = fmaf(v0.x, n0, acc.x); acc.y = fmaf(v0.y, n0, acc.y);
        acc.z = fmaf(v0.z, n0, acc.z); acc.w = fmaf(v0.w, n0, acc.w);
    }

    // apply factored dinv[d]
    acc.x *= dv; acc.y *= dv; acc.z *= dv; acc.w *= dv;

    if (DO_LN) {
        float4 bb = *(const float4*)(b2 + lane * 4);
        acc.x += bb.x; acc.y += bb.y; acc.z += bb.z; acc.w += bb.w;

        float s = acc.x + acc.y + acc.z + acc.w;
#pragma unroll
        for (int o = 16; o > 0; o >>= 1) s += __shfl_xor_sync(0xFFFFFFFFu, s, o);
        float mu = s * (1.0f / DIN);

        float dx = acc.x - mu, dy = acc.y - mu, dz = acc.z - mu, dw = acc.w - mu;
        float q = dx * dx + dy * dy + dz * dz + dw * dw;
#pragma unroll
        for (int o = 16; o > 0; o >>= 1) q += __shfl_xor_sync(0xFFFFFFFFu, q, o);
        float rstd = rsqrtf(q * (1.0f / DIN) + 1e-5f);

        float4 g  = *(const float4*)(gamma + lane * 4);
        float4 bt = *(const float4*)(beta + lane * 4);
        float4 o4;
        o4.x = dx * rstd * g.x + bt.x;
        o4.y = dy * rstd * g.y + bt.y;
        o4.z = dz * rstd * g.z + bt.z;
        o4.w = dw * rstd * g.w + bt.w;
        *(float4*)((float*)outb + (size_t)node * DIN + lane * 4) = o4;
    } else {
        __half2 h0 = __floats2half2_rn(acc.x, acc.y);
        __half2 h1 = __floats2half2_rn(acc.z, acc.w);
        uint2 pk = make_uint2(*(uint32_t*)&h0, *(uint32_t*)&h1);
        ((uint2*)outb)[node * 32 + lane] = pk;
    }
}

// ---------------- fused MLP: p = relu(A@W1^T + b1) @ W2^T --------------------
__device__ __forceinline__ void mma_f16(float c[4], const uint32_t a[4],
                                        const uint32_t b[2]) {
    asm volatile(
        "mma.sync.aligned.m16n8k16.row.col.f32.f16.f16.f32 "
        "{%0,%1,%2,%3}, {%4,%5,%6,%7}, {%8,%9}, {%0,%1,%2,%3};"
        : "+f"(c[0]), "+f"(c[1]), "+f"(c[2]), "+f"(c[3])
        : "r"(a[0]), "r"(a[1]), "r"(a[2]), "r"(a[3]), "r"(b[0]), "r"(b[1]));
}

#define AS_ST 68    // uints per row (64 data + 4 pad): 128-half rows
#define W2_ST 132   // uints per row (128 data + 4 pad): 256-half rows
#define SM_A  0
#define SM_W  (SM_A + 128 * AS_ST)
#define SM_H  (SM_W + 128 * W2_ST)
#define SM_TOTAL_U (SM_H + 128 * W2_ST)

__global__ __launch_bounds__(256, 1)
void fused_mlp_kernel(const __half* __restrict__ A,
                      const __half* __restrict__ W1,
                      const __half* __restrict__ W2,
                      const float* __restrict__ b1,
                      __half* __restrict__ P, int M) {
    extern __shared__ uint32_t sm[];
    uint32_t* A_s = sm + SM_A;
    uint32_t* W_s = sm + SM_W;
    uint32_t* H_s = sm + SM_H;

    const int tid  = threadIdx.x;
    const int lane = tid & 31;
    const int warp = tid >> 5;
    const int wm   = warp & 3;
    const int wn   = warp >> 2;
    const int gid  = lane >> 2;
    const int tig  = lane & 3;
    const int m0   = blockIdx.x * 128;

#pragma unroll
    for (int l = 0; l < 8; l++) {
        int idx = tid + l * 256;
        int row = idx >> 4;
        int q   = idx & 15;
        uint4 v = (m0 + row < M)
                ? *(const uint4*)(A + (size_t)(m0 + row) * DIN + q * 8)
                : make_uint4(0u, 0u, 0u, 0u);
        *(uint4*)&A_s[row * AS_ST + q * 4] = v;
    }

    for (int nh = 0; nh < 2; nh++) {
#pragma unroll
        for (int l = 0; l < 8; l++) {
            int idx = tid + l * 256;
            int row = idx >> 4;
            int q   = idx & 15;
            uint4 v = *(const uint4*)(W1 + (size_t)(nh * 128 + row) * DIN + q * 8);
            *(uint4*)&W_s[row * AS_ST + q * 4] = v;
        }
        __syncthreads();

        float acc[2][8][4];
#pragma unroll
        for (int i = 0; i < 2; i++)
#pragma unroll
            for (int j = 0; j < 8; j++)
#pragma unroll
                for (int q = 0; q < 4; q++) acc[i][j][q] = 0.f;

#pragma unroll
        for (int s = 0; s < 8; s++) {
            const int k2 = s * 8;
            uint32_t af[2][4];
#pragma unroll
            for (int mt = 0; mt < 2; mt++) {
                int rb = wm * 32 + mt * 16;
                af[mt][0] = A_s[(rb + gid) * AS_ST + k2 + tig];
                af[mt][1] = A_s[(rb + gid + 8) * AS_ST + k2 + tig];
                af[mt][2] = A_s[(rb + gid) * AS_ST + k2 + tig + 4];
                af[mt][3] = A_s[(rb + gid + 8) * AS_ST + k2 + tig + 4];
            }
            uint32_t bf[8][2];
#pragma unroll
            for (int ntl = 0; ntl < 8; ntl++) {
                int col = wn * 64 + ntl * 8 + gid;
                bf[ntl][0] = W_s[col * AS_ST + k2 + tig];
                bf[ntl][1] = W_s[col * AS_ST + k2 + tig + 4];
            }
#pragma unroll
            for (int mt = 0; mt < 2; mt++)
#pragma unroll
                for (int ntl = 0; ntl < 8; ntl++)
                    mma_f16(acc[mt][ntl], af[mt], bf[ntl]);
        }
        __syncthreads();

#pragma unroll
        for (int mt = 0; mt < 2; mt++) {
            int r0 = wm * 32 + mt * 16 + gid;
            int r1 = r0 + 8;
#pragma unroll
            for (int ntl = 0; ntl < 8; ntl++) {
                int colL = wn * 64 + ntl * 8 + tig * 2;
                int colG = nh * 128 + colL;
                float bx = b1[colG], by = b1[colG + 1];
                float2 v0 = make_float2(fmaxf(acc[mt][ntl][0] + bx, 0.f),
                                        fmaxf(acc[mt][ntl][1] + by, 0.f));
                float2 v1 = make_float2(fmaxf(acc[mt][ntl][2] + bx, 0.f),
                                        fmaxf(acc[mt][ntl][3] + by, 0.f));
                __half2 h0 = __floats2half2_rn(v0.x, v0.y);
                __half2 h1 = __floats2half2_rn(v1.x, v1.y);
                H_s[r0 * W2_ST + (colG >> 1)] = *(uint32_t*)&h0;
                H_s[r1 * W2_ST + (colG >> 1)] = *(uint32_t*)&h1;
            }
        }
    }

#pragma unroll
    for (int l = 0; l < 16; l++) {
        int idx = tid + l * 256;
        int row = idx >> 5;
        int q   = idx & 31;
        uint4 v = *(const uint4*)(W2 + (size_t)row * DH + q * 8);
        *(uint4*)&W_s[row * W2_ST + q * 4] = v;
    }
    __syncthreads();

    float acc2[2][8][4];
#pragma unroll
    for (int i = 0; i < 2; i++)
#pragma unroll
        for (int j = 0; j < 8; j++)
#pragma unroll
            for (int q = 0; q < 4; q++) acc2[i][j][q] = 0.f;

#pragma unroll
    for (int s = 0; s < 16; s++) {
        const int k2 = s * 8;
        uint32_t af[2][4];
#pragma unroll
        for (int mt = 0; mt < 2; mt++) {
            int rb = wm * 32 + mt * 16;
            af[mt][0] = H_s[(rb + gid) * W2_ST + k2 + tig];
            af[mt][1] = H_s[(rb + gid + 8) * W2_ST + k2 + tig];
            af[mt][2] = H_s[(rb + gid) * W2_ST + k2 + tig + 4];
            af[mt][3] = H_s[(rb + gid + 8) * W2_ST + k2 + tig + 4];
        }
        uint32_t bf[8][2];
#pragma unroll
        for (int ntl = 0; ntl < 8; ntl++) {
            int col = wn * 64 + ntl * 8 + gid;
            bf[ntl][0] = W_s[col * W2_ST + k2 + tig];
            bf[ntl][1] = W_s[col * W2_ST + k2 + tig + 4];
        }
#pragma unroll
        for (int mt = 0; mt < 2; mt++)
#pragma unroll
            for (int ntl = 0; ntl < 8; ntl++)
                mma_f16(acc2[mt][ntl], af[mt], bf[ntl]);
    }

#pragma unroll
    for (int mt = 0; mt < 2; mt++) {
        int row0 = m0 + wm * 32 + mt * 16 + gid;
        int row1 = row0 + 8;
#pragma unroll
        for (int ntl = 0; ntl < 8; ntl++) {
            int col = wn * 64 + ntl * 8 + tig * 2;
            __half2 h0 = __floats2half2_rn(acc2[mt][ntl][0], acc2[mt][ntl][1]);
            __half2 h1 = __floats2half2_rn(acc2[mt][ntl][2], acc2[mt][ntl][3]);
            if (row0 < M) *(__half2*)(P + (size_t)row0 * DIN + col) = h0;
            if (row1 < M) *(__half2*)(P + (size_t)row1 * DIN + col) = h1;
        }
    }
}

// -----------------------------------------------------------------------------
extern "C" void kernel_launch(void* const* d_in, const int* in_sizes, int n_in,
                              void* d_out, int out_size) {
    const float* x     = (const float*)d_in[0];
    const void*  ei    = d_in[1];
    const float* ew    = (const float*)d_in[2];
    const float* W1    = (const float*)d_in[3];
    const float* b1    = (const float*)d_in[4];
    const float* W2    = (const float*)d_in[5];
    const float* b2    = (const float*)d_in[6];
    const float* gamma = (const float*)d_in[7];
    const float* beta  = (const float*)d_in[8];
    float*       out   = (float*)d_out;

    float *dinv;
    __half *xh, *a1h, *ph, *w1h, *w2h;
    int *cnt, *rowstart;
    uint2 *stage;
    int2 *csr;
    cudaGetSymbolAddress((void**)&dinv,     g_dinv);
    cudaGetSymbolAddress((void**)&xh,       g_xh);
    cudaGetSymbolAddress((void**)&a1h,      g_a1h);
    cudaGetSymbolAddress((void**)&ph,       g_ph);
    cudaGetSymbolAddress((void**)&w1h,      g_w1h);
    cudaGetSymbolAddress((void**)&w2h,      g_w2h);
    cudaGetSymbolAddress((void**)&cnt,      g_count);
    cudaGetSymbolAddress((void**)&rowstart, g_rowstart);
    cudaGetSymbolAddress((void**)&stage,    g_stage);
    cudaGetSymbolAddress((void**)&csr,      g_csr);

    const int n = NN, e = EE;
    const int smem_bytes = SM_TOTAL_U * 4;
    static bool attr_set = false;
    if (!attr_set) {
        cudaFuncSetAttribute(fused_mlp_kernel,
                             cudaFuncAttributeMaxDynamicSharedMemorySize,
                             smem_bytes);
        attr_set = true;
    }

    // 1. prep: zero scratch, detect dtype, x/W1/W2 -> fp16
    prep_kernel<<<1024, 256>>>((const int*)ei, x, W1, W2, dinv, cnt);

    // 2. degree + counts + stage (src,dst,rank) — 2 edges/thread
    convert_deg_kernel<<<(e / 2 + 255) / 256, 256>>>(ei, ew, dinv, cnt, stage, e);

    // 3. single-pass scan (+dinv)
    scan_lookback_kernel<<<NBLK, 256>>>(cnt, dinv, rowstart, n);

    // 4. CSR fill: pos = rowstart + rank; store (s, w*dinv[s]) — 2 edges/thread
    csr_fill_kernel<<<(e / 2 + 255) / 256, 256>>>(stage, ew, dinv, rowstart, csr, e);

    // 5. agg1 = A_norm @ x  (fp16 gather -> fp16)
    gather_kernel<0><<<(n * 32 + 255) / 256, 256>>>(rowstart, csr, dinv, xh,
                                                    nullptr, nullptr, nullptr,
                                                    a1h, n);

    // 6. p = relu(agg1 @ W1^T + b1) @ W2^T   (fused MLP)
    fused_mlp_kernel<<<(n + 127) / 128, 256, smem_bytes>>>(a1h, w1h, w2h, b1,
                                                           ph, n);

    // 7. out = LN(A_norm @ p + b2) * gamma + beta
    gather_kernel<1><<<(n * 32 + 255) / 256, 256>>>(rowstart, csr, dinv, ph,
                                                    b2, gamma, beta, out, n);
}